// round 6
// baseline (speedup 1.0000x reference)
#include <cuda_runtime.h>
#include <math.h>

// Problem constants (fixed shapes)
#define NNODES  100000
#define NHEDGES 50000
#define NINC    300000
#define NGRAPHS 1024
#define DIN     49
#define DIM     512
#define NLAYERS 3

// ---------------------------------------------------------------------------
// Scratch (static device globals; no runtime allocation allowed)
// ---------------------------------------------------------------------------
__device__ __align__(16) float g_x[(size_t)NNODES * DIM];      // node features
__device__ __align__(16) float g_A[(size_t)NHEDGES * DIM];     // hedge aggregate / B
__device__ __align__(16) float g_msg[(size_t)NHEDGES * DIM];   // hedge_msg
__device__ __align__(16) float g_nacc[(size_t)NNODES * DIM];   // node accumulator
__device__ int   g_hcnt[NHEDGES];
__device__ int   g_ncnt[NNODES];
__device__ int   g_gcnt[NGRAPHS];
__device__ __align__(16) float g_gsum[NGRAPHS * DIM];
__device__ __align__(16) float g_gavg[NGRAPHS * DIM];

// ---------------------------------------------------------------------------
// Small PTX helpers (no external headers)
// ---------------------------------------------------------------------------
__device__ __forceinline__ void cp_async16(void* smem_dst, const void* gmem_src)
{
    unsigned s = (unsigned)__cvta_generic_to_shared(smem_dst);
    asm volatile("cp.async.cg.shared.global [%0], [%1], 16;\n" :: "r"(s), "l"(gmem_src));
}
__device__ __forceinline__ void cp_async_commit() { asm volatile("cp.async.commit_group;\n"); }
__device__ __forceinline__ void cp_async_wait_all() { asm volatile("cp.async.wait_all;\n" ::: "memory"); }

__device__ __forceinline__ void red_add_v4(float* p, float4 v)
{
#if defined(__CUDA_ARCH__) && (__CUDA_ARCH__ >= 900)
    asm volatile("red.global.add.v4.f32 [%0], {%1, %2, %3, %4};\n"
                 :: "l"(p), "f"(v.x), "f"(v.y), "f"(v.z), "f"(v.w) : "memory");
#else
    atomicAdd(p + 0, v.x);
    atomicAdd(p + 1, v.y);
    atomicAdd(p + 2, v.z);
    atomicAdd(p + 3, v.w);
#endif
}

// ---------------------------------------------------------------------------
// Degree / count kernel (fused): incidence degrees + per-graph node counts
// ---------------------------------------------------------------------------
__global__ void count_all_kernel(const int* __restrict__ node_idx,
                                 const int* __restrict__ hedge_idx,
                                 const int* __restrict__ batch)
{
    int e = blockIdx.x * blockDim.x + threadIdx.x;
    if (e < NINC) {
        atomicAdd(&g_ncnt[node_idx[e]], 1);
        atomicAdd(&g_hcnt[hedge_idx[e]], 1);
    }
    if (e < NNODES) {
        atomicAdd(&g_gcnt[batch[e]], 1);
    }
}

// ---------------------------------------------------------------------------
// Input GEMM: x = node_features[100000,49] @ in_w[49,512] + in_b
// ---------------------------------------------------------------------------
__global__ __launch_bounds__(128)
void input_gemm_kernel(const float* __restrict__ nf,
                       const float* __restrict__ w,
                       const float* __restrict__ b)
{
    __shared__ float snf[16 * DIN];
    const int r0 = blockIdx.x * 16;
    const int tid = threadIdx.x;
    for (int i = tid; i < 16 * DIN; i += 128)
        snf[i] = nf[(size_t)r0 * DIN + i];   // rows contiguous
    __syncthreads();

    const int c0 = tid * 4;
    float4 acc[16];
#pragma unroll
    for (int r = 0; r < 16; r++) acc[r] = make_float4(0.f, 0.f, 0.f, 0.f);

    for (int k = 0; k < DIN; k++) {
        float4 w4 = *(const float4*)&w[(size_t)k * DIM + c0];
#pragma unroll
        for (int r = 0; r < 16; r++) {
            float a = snf[r * DIN + k];
            acc[r].x = fmaf(a, w4.x, acc[r].x);
            acc[r].y = fmaf(a, w4.y, acc[r].y);
            acc[r].z = fmaf(a, w4.z, acc[r].z);
            acc[r].w = fmaf(a, w4.w, acc[r].w);
        }
    }
    float4 bb = *(const float4*)&b[c0];
#pragma unroll
    for (int r = 0; r < 16; r++) {
        float4 v = acc[r];
        v.x += bb.x; v.y += bb.y; v.z += bb.z; v.w += bb.w;
        *(float4*)&g_x[(size_t)(r0 + r) * DIM + c0] = v;
    }
}

// ---------------------------------------------------------------------------
// SpMM scatter: dst[didx[e]] += src[sidx[e]]  (vector red, 2 edges / 256-thr block)
// ---------------------------------------------------------------------------
__global__ __launch_bounds__(256)
void spmm_kernel(const int* __restrict__ sidx, const int* __restrict__ didx,
                 const float* __restrict__ src, float* __restrict__ dst)
{
    int e = blockIdx.x * 2 + (threadIdx.x >> 7);
    if (e >= NINC) return;
    int lane = (threadIdx.x & 127) << 2;
    int s = sidx[e], d = didx[e];
    float4 v = *(const float4*)&src[(size_t)s * DIM + lane];
    red_add_v4(&dst[(size_t)d * DIM + lane], v);
}

// ---------------------------------------------------------------------------
// SGEMM: C[M,512] = A[M,512] @ W[512,512]  (+ per-mode epilogue)
// MODE 0: plain       MODE 1: hedge_msg epilogue    MODE 2: + column bias
// 128x128x16 tiles, 256 threads, 8x8 microtile, 2-stage double buffering.
// A-tile: register-staged (needs transpose). B-tile: cp.async.
// ---------------------------------------------------------------------------
template<int MODE>
__global__ __launch_bounds__(256, 2)
void sgemm_kernel(const float* __restrict__ A, const float* __restrict__ W,
                  float* __restrict__ C, int M,
                  const float* __restrict__ colbias,
                  const int* __restrict__ cnt,
                  const int* __restrict__ types,
                  const float* __restrict__ type_emb)
{
    __shared__ __align__(16) float sA[2][16][128];
    __shared__ __align__(16) float sB[2][16][128];
    const int tid  = threadIdx.x;
    const int tx   = tid & 15;
    const int ty   = tid >> 4;
    const int row0 = blockIdx.y * 128;
    const int col0 = blockIdx.x * 128;

    float acc[8][8];
#pragma unroll
    for (int i = 0; i < 8; i++)
#pragma unroll
        for (int j = 0; j < 8; j++) acc[i][j] = 0.f;

    const int aRow = tid >> 2;         // 0..63
    const int aK4  = (tid & 3) << 2;   // 0,4,8,12
    const int bK   = tid >> 5;         // 0..7
    const int bN4  = (tid & 31) << 2;  // 0..124

    float4 va[2];

    // ---- prologue: stage K-tile 0 into buffer 0
#pragma unroll
    for (int rr = 0; rr < 2; rr++) {
        int gr = row0 + aRow + rr * 64;
        va[rr] = make_float4(0.f, 0.f, 0.f, 0.f);
        if (gr < M) va[rr] = *(const float4*)&A[(size_t)gr * DIM + aK4];
    }
#pragma unroll
    for (int kk = 0; kk < 2; kk++) {
        int k = bK + kk * 8;
        cp_async16(&sB[0][k][bN4], &W[(size_t)k * DIM + col0 + bN4]);
    }
    cp_async_commit();
#pragma unroll
    for (int rr = 0; rr < 2; rr++) {
        int r = aRow + rr * 64;
        sA[0][aK4 + 0][r] = va[rr].x;
        sA[0][aK4 + 1][r] = va[rr].y;
        sA[0][aK4 + 2][r] = va[rr].z;
        sA[0][aK4 + 3][r] = va[rr].w;
    }
    cp_async_wait_all();
    __syncthreads();

    const int NT = DIM / 16;  // 32 K-tiles
    for (int t = 0; t < NT; t++) {
        const int cur = t & 1;
        const int nxt = cur ^ 1;
        // ---- prefetch K-tile t+1: A -> registers, B -> smem via cp.async
        if (t + 1 < NT) {
            const int k0 = (t + 1) * 16;
#pragma unroll
            for (int rr = 0; rr < 2; rr++) {
                int gr = row0 + aRow + rr * 64;
                va[rr] = make_float4(0.f, 0.f, 0.f, 0.f);
                if (gr < M) va[rr] = *(const float4*)&A[(size_t)gr * DIM + k0 + aK4];
            }
#pragma unroll
            for (int kk = 0; kk < 2; kk++) {
                int k = bK + kk * 8;
                cp_async16(&sB[nxt][k][bN4], &W[(size_t)(k0 + k) * DIM + col0 + bN4]);
            }
            cp_async_commit();
        }
        // ---- compute on current buffer
#pragma unroll
        for (int k = 0; k < 16; k++) {
            float4 a0 = *(const float4*)&sA[cur][k][ty * 8];
            float4 a1 = *(const float4*)&sA[cur][k][ty * 8 + 4];
            float4 b0 = *(const float4*)&sB[cur][k][tx * 8];
            float4 b1 = *(const float4*)&sB[cur][k][tx * 8 + 4];
            float ra[8] = {a0.x, a0.y, a0.z, a0.w, a1.x, a1.y, a1.z, a1.w};
            float rb[8] = {b0.x, b0.y, b0.z, b0.w, b1.x, b1.y, b1.z, b1.w};
#pragma unroll
            for (int i = 0; i < 8; i++)
#pragma unroll
                for (int j = 0; j < 8; j++)
                    acc[i][j] = fmaf(ra[i], rb[j], acc[i][j]);
        }
        // ---- stage t+1 A registers -> alternate smem buffer, drain cp.async
        if (t + 1 < NT) {
#pragma unroll
            for (int rr = 0; rr < 2; rr++) {
                int r = aRow + rr * 64;
                sA[nxt][aK4 + 0][r] = va[rr].x;
                sA[nxt][aK4 + 1][r] = va[rr].y;
                sA[nxt][aK4 + 2][r] = va[rr].z;
                sA[nxt][aK4 + 3][r] = va[rr].w;
            }
            cp_async_wait_all();
            __syncthreads();
        }
    }

    // ---- epilogue
#pragma unroll
    for (int i = 0; i < 8; i++) {
        int r = row0 + ty * 8 + i;
        if (r >= M) continue;
        float invd = 1.f, hb = 0.f;
        const float* te = nullptr;
        if (MODE == 1) {
            int cn = cnt[r];
            invd = 1.f / (float)(cn > 0 ? cn : 1);
            hb   = (cn > 0) ? 1.f : 0.f;
            te   = type_emb + (size_t)types[r] * DIM;
        }
#pragma unroll
        for (int jj = 0; jj < 2; jj++) {
            int c = col0 + tx * 8 + jj * 4;
            float4 v = make_float4(acc[i][jj * 4 + 0], acc[i][jj * 4 + 1],
                                   acc[i][jj * 4 + 2], acc[i][jj * 4 + 3]);
            if (MODE == 1) {
                v.x = v.x * invd + hb * colbias[c + 0] + te[c + 0];
                v.y = v.y * invd + hb * colbias[c + 1] + te[c + 1];
                v.z = v.z * invd + hb * colbias[c + 2] + te[c + 2];
                v.w = v.w * invd + hb * colbias[c + 3] + te[c + 3];
            } else if (MODE == 2) {
                v.x += colbias[c + 0];
                v.y += colbias[c + 1];
                v.z += colbias[c + 2];
                v.w += colbias[c + 3];
            }
            *(float4*)&C[(size_t)r * DIM + c] = v;
        }
    }
}

// ---------------------------------------------------------------------------
// Node epilogue: out = gelu(layernorm(x + nacc/deg + b2))  (one block per row)
// ---------------------------------------------------------------------------
__device__ __forceinline__ float gelu_exact(float y)
{
    return 0.5f * y * (1.f + erff(y * 0.70710678118654752440f));
}

__global__ __launch_bounds__(128)
void node_epilogue_kernel(const float* __restrict__ xin,
                          float* __restrict__ xout,
                          const float* __restrict__ b2,
                          const float* __restrict__ lng,
                          const float* __restrict__ lnb)
{
    const int n = blockIdx.x;
    const int t = threadIdx.x;
    const size_t base = (size_t)n * DIM + t * 4;
    const int cn = g_ncnt[n];
    const float invd = 1.f / (float)(cn > 0 ? cn : 1);

    float4 a  = *(const float4*)&g_nacc[base];
    float4 xi = *(const float4*)&xin[base];
    float4 bb = *(const float4*)&b2[t * 4];
    float4 v;
    v.x = fmaf(a.x, invd, bb.x) + xi.x;
    v.y = fmaf(a.y, invd, bb.y) + xi.y;
    v.z = fmaf(a.z, invd, bb.z) + xi.z;
    v.w = fmaf(a.w, invd, bb.w) + xi.w;

    float s = v.x + v.y + v.z + v.w;
    float q = v.x * v.x + v.y * v.y + v.z * v.z + v.w * v.w;
#pragma unroll
    for (int o = 16; o; o >>= 1) {
        s += __shfl_xor_sync(0xffffffffu, s, o);
        q += __shfl_xor_sync(0xffffffffu, q, o);
    }
    __shared__ float ss[4], sq[4];
    if ((t & 31) == 0) { ss[t >> 5] = s; sq[t >> 5] = q; }
    __syncthreads();
    s = ss[0] + ss[1] + ss[2] + ss[3];
    q = sq[0] + sq[1] + sq[2] + sq[3];

    const float mean = s * (1.f / 512.f);
    const float var  = q * (1.f / 512.f) - mean * mean;
    const float rstd = rsqrtf(var + 1e-5f);

    float4 gg = *(const float4*)&lng[t * 4];
    float4 lb = *(const float4*)&lnb[t * 4];
    float4 o;
    o.x = gelu_exact(fmaf((v.x - mean) * rstd, gg.x, lb.x));
    o.y = gelu_exact(fmaf((v.y - mean) * rstd, gg.y, lb.y));
    o.z = gelu_exact(fmaf((v.z - mean) * rstd, gg.z, lb.z));
    o.w = gelu_exact(fmaf((v.w - mean) * rstd, gg.w, lb.w));
    *(float4*)&xout[base] = o;
}

// ---------------------------------------------------------------------------
// Graph pooling
// ---------------------------------------------------------------------------
__global__ __launch_bounds__(128)
void pool_kernel(const float* __restrict__ xsrc, const int* __restrict__ batch)
{
    const int n = blockIdx.x;
    const int t = threadIdx.x;
    const int b = batch[n];
    float4 v = *(const float4*)&xsrc[(size_t)n * DIM + t * 4];
    red_add_v4(&g_gsum[(size_t)b * DIM + t * 4], v);
}

__global__ void gavg_kernel()
{
    int i = blockIdx.x * blockDim.x + threadIdx.x;
    if (i < NGRAPHS * DIM) {
        int g = i >> 9;
        int cn = g_gcnt[g];
        g_gavg[i] = g_gsum[i] / (float)(cn > 0 ? cn : 1);
    }
}

__global__ void batch_copy_kernel(const int* __restrict__ batch, float* __restrict__ out)
{
    int n = blockIdx.x * blockDim.x + threadIdx.x;
    if (n < NNODES) out[n] = (float)batch[n];
}

// ---------------------------------------------------------------------------
// Launch
// ---------------------------------------------------------------------------
extern "C" void kernel_launch(void* const* d_in, const int* in_sizes, int n_in,
                              void* d_out, int out_size)
{
    const float* nf        = (const float*)d_in[0];
    const int*   node_idx  = (const int*)d_in[1];
    const int*   hedge_idx = (const int*)d_in[2];
    const int*   htypes    = (const int*)d_in[3];
    const int*   batch     = (const int*)d_in[4];

    // Locate weight block robustly (optional scalar num_graphs input may be at index 5)
    int w = 5;
    for (int i = 5; i < n_in; i++) {
        if (in_sizes[i] == DIN * DIM) { w = i; break; }
    }
    const float* in_w     = (const float*)d_in[w + 0];
    const float* in_b     = (const float*)d_in[w + 1];
    const float* type_emb = (const float*)d_in[w + 2];
    const float* l1_w     = (const float*)d_in[w + 3];
    const float* l1_b     = (const float*)d_in[w + 4];
    const float* l2_w     = (const float*)d_in[w + 5];
    const float* l2_b     = (const float*)d_in[w + 6];
    const float* ln_g     = (const float*)d_in[w + 7];
    const float* ln_b     = (const float*)d_in[w + 8];
    const float* out_w    = (const float*)d_in[w + 9];
    const float* out_b    = (const float*)d_in[w + 10];

    float* out = (float*)d_out;

    // Symbol addresses (lookup only; capture-safe)
    void *pX, *pA, *pMsg, *pNacc, *pHc, *pNc, *pGc, *pGs, *pGa;
    cudaGetSymbolAddress(&pX, g_x);
    cudaGetSymbolAddress(&pA, g_A);
    cudaGetSymbolAddress(&pMsg, g_msg);
    cudaGetSymbolAddress(&pNacc, g_nacc);
    cudaGetSymbolAddress(&pHc, g_hcnt);
    cudaGetSymbolAddress(&pNc, g_ncnt);
    cudaGetSymbolAddress(&pGc, g_gcnt);
    cudaGetSymbolAddress(&pGs, g_gsum);
    cudaGetSymbolAddress(&pGa, g_gavg);

    const size_t GSZ = (size_t)NGRAPHS * DIM;           // 524288
    const size_t NSZ = (size_t)NNODES * DIM;            // 51200000
    const bool has_nodes = (size_t)out_size >= GSZ + NSZ;
    const bool has_batch = (size_t)out_size >= GSZ + NSZ + NNODES;
    float* nodes_out = has_nodes ? out + GSZ : (float*)pX;

    // Degrees (fused counts)
    cudaMemsetAsync(pHc, 0, sizeof(int) * NHEDGES, 0);
    cudaMemsetAsync(pNc, 0, sizeof(int) * NNODES, 0);
    cudaMemsetAsync(pGc, 0, sizeof(int) * NGRAPHS, 0);
    count_all_kernel<<<(NINC + 255) / 256, 256>>>(node_idx, hedge_idx, batch);

    // Input projection
    input_gemm_kernel<<<NNODES / 16, 128>>>(nf, in_w, in_b);

    const dim3 gemm_grid_h(4, (NHEDGES + 127) / 128);

    for (int i = 0; i < NLAYERS; i++) {
        // A = segment_sum(x[node_idx]) over hedges
        cudaMemsetAsync(pA, 0, sizeof(float) * NHEDGES * DIM, 0);
        spmm_kernel<<<(NINC + 1) / 2, 256>>>(node_idx, hedge_idx,
                                             (const float*)pX, (float*)pA);
        // msg = (A@W1 + cnt*b1)/clip(cnt,1) + type_emb[type]
        sgemm_kernel<1><<<gemm_grid_h, 256>>>(
            (const float*)pA, l1_w + (size_t)i * DIM * DIM, (float*)pMsg, NHEDGES,
            l1_b + (size_t)i * DIM, (const int*)pHc, htypes, type_emb);
        // B = msg @ W2   (reuse g_A)
        sgemm_kernel<0><<<gemm_grid_h, 256>>>(
            (const float*)pMsg, l2_w + (size_t)i * DIM * DIM, (float*)pA, NHEDGES,
            nullptr, nullptr, nullptr, nullptr);
        // nacc = segment_sum(B[hedge_idx]) over nodes
        cudaMemsetAsync(pNacc, 0, sizeof(float) * NSZ, 0);
        spmm_kernel<<<(NINC + 1) / 2, 256>>>(hedge_idx, node_idx,
                                             (const float*)pA, (float*)pNacc);
        // x = gelu(LN(x + nacc/deg + b2))
        float* xo = (i == NLAYERS - 1) ? nodes_out : (float*)pX;
        node_epilogue_kernel<<<NNODES, 128>>>(
            (const float*)pX, xo,
            l2_b + (size_t)i * DIM, ln_g + (size_t)i * DIM, ln_b + (size_t)i * DIM);
    }

    // Graph pooling + output projection
    cudaMemsetAsync(pGs, 0, sizeof(float) * GSZ, 0);
    pool_kernel<<<NNODES, 128>>>((const float*)nodes_out, batch);
    gavg_kernel<<<(NGRAPHS * DIM + 255) / 256, 256>>>();
    sgemm_kernel<2><<<dim3(4, NGRAPHS / 128), 256>>>(
        (const float*)pGa, out_w, out, NGRAPHS,
        out_b, nullptr, nullptr, nullptr);

    if (has_batch)
        batch_copy_kernel<<<(NNODES + 255) / 256, 256>>>(batch, out + GSZ + NSZ);
}

// round 14
// speedup vs baseline: 1.0890x; 1.0890x over previous
#include <cuda_runtime.h>
#include <math.h>

// Problem constants (fixed shapes)
#define NNODES  100000
#define NHEDGES 50000
#define NINC    300000
#define NGRAPHS 1024
#define DIN     49
#define DIM     512
#define NLAYERS 3

// ---------------------------------------------------------------------------
// Scratch (static device globals; no runtime allocation allowed)
// ---------------------------------------------------------------------------
__device__ __align__(16) float g_x[(size_t)NNODES * DIM];      // node features
__device__ __align__(16) float g_A[(size_t)NHEDGES * DIM];     // hedge aggregate / B
__device__ __align__(16) float g_msg[(size_t)NHEDGES * DIM];   // hedge_msg
__device__ __align__(16) float g_nacc[(size_t)NNODES * DIM];   // node accumulator
__device__ int   g_hcnt[NHEDGES];
__device__ int   g_ncnt[NNODES];
__device__ int   g_gcnt[NGRAPHS];
__device__ __align__(16) float g_gsum[NGRAPHS * DIM];
__device__ __align__(16) float g_gavg[NGRAPHS * DIM];

// ---------------------------------------------------------------------------
// Small PTX helpers (no external headers)
// ---------------------------------------------------------------------------
__device__ __forceinline__ void cp_async16(void* smem_dst, const void* gmem_src)
{
    unsigned s = (unsigned)__cvta_generic_to_shared(smem_dst);
    asm volatile("cp.async.cg.shared.global [%0], [%1], 16;\n" :: "r"(s), "l"(gmem_src));
}
__device__ __forceinline__ void cp_async_commit() { asm volatile("cp.async.commit_group;\n"); }
__device__ __forceinline__ void cp_async_wait_all() { asm volatile("cp.async.wait_all;\n" ::: "memory"); }

__device__ __forceinline__ void red_add_v4(float* p, float4 v)
{
#if defined(__CUDA_ARCH__) && (__CUDA_ARCH__ >= 900)
    asm volatile("red.global.add.v4.f32 [%0], {%1, %2, %3, %4};\n"
                 :: "l"(p), "f"(v.x), "f"(v.y), "f"(v.z), "f"(v.w) : "memory");
#else
    atomicAdd(p + 0, v.x);
    atomicAdd(p + 1, v.y);
    atomicAdd(p + 2, v.z);
    atomicAdd(p + 3, v.w);
#endif
}

// ---------------------------------------------------------------------------
// Degree / count kernel (fused): incidence degrees + per-graph node counts
// ---------------------------------------------------------------------------
__global__ void count_all_kernel(const int* __restrict__ node_idx,
                                 const int* __restrict__ hedge_idx,
                                 const int* __restrict__ batch)
{
    int e = blockIdx.x * blockDim.x + threadIdx.x;
    if (e < NINC) {
        atomicAdd(&g_ncnt[node_idx[e]], 1);
        atomicAdd(&g_hcnt[hedge_idx[e]], 1);
    }
    if (e < NNODES) {
        atomicAdd(&g_gcnt[batch[e]], 1);
    }
}

// ---------------------------------------------------------------------------
// Input GEMM: x = node_features[100000,49] @ in_w[49,512] + in_b
// ---------------------------------------------------------------------------
__global__ __launch_bounds__(128)
void input_gemm_kernel(const float* __restrict__ nf,
                       const float* __restrict__ w,
                       const float* __restrict__ b)
{
    __shared__ float snf[16 * DIN];
    const int r0 = blockIdx.x * 16;
    const int tid = threadIdx.x;
    for (int i = tid; i < 16 * DIN; i += 128)
        snf[i] = nf[(size_t)r0 * DIN + i];   // rows contiguous
    __syncthreads();

    const int c0 = tid * 4;
    float4 acc[16];
#pragma unroll
    for (int r = 0; r < 16; r++) acc[r] = make_float4(0.f, 0.f, 0.f, 0.f);

    for (int k = 0; k < DIN; k++) {
        float4 w4 = *(const float4*)&w[(size_t)k * DIM + c0];
#pragma unroll
        for (int r = 0; r < 16; r++) {
            float a = snf[r * DIN + k];
            acc[r].x = fmaf(a, w4.x, acc[r].x);
            acc[r].y = fmaf(a, w4.y, acc[r].y);
            acc[r].z = fmaf(a, w4.z, acc[r].z);
            acc[r].w = fmaf(a, w4.w, acc[r].w);
        }
    }
    float4 bb = *(const float4*)&b[c0];
#pragma unroll
    for (int r = 0; r < 16; r++) {
        float4 v = acc[r];
        v.x += bb.x; v.y += bb.y; v.z += bb.z; v.w += bb.w;
        *(float4*)&g_x[(size_t)(r0 + r) * DIM + c0] = v;
    }
}

// ---------------------------------------------------------------------------
// SpMM scatter: dst[didx[e]] += src[sidx[e]]  (vector red, 2 edges / 256-thr block)
// ---------------------------------------------------------------------------
__global__ __launch_bounds__(256)
void spmm_kernel(const int* __restrict__ sidx, const int* __restrict__ didx,
                 const float* __restrict__ src, float* __restrict__ dst)
{
    int e = blockIdx.x * 2 + (threadIdx.x >> 7);
    if (e >= NINC) return;
    int lane = (threadIdx.x & 127) << 2;
    int s = sidx[e], d = didx[e];
    float4 v = *(const float4*)&src[(size_t)s * DIM + lane];
    red_add_v4(&dst[(size_t)d * DIM + lane], v);
}

// ---------------------------------------------------------------------------
// SGEMM: C[M,512] = A[M,512] @ W[512,512]  (+ per-mode epilogue)
// MODE 0: plain       MODE 1: hedge_msg epilogue    MODE 2: + column bias
// 128x128x16 tiles, 256 threads, 8x8 microtile, 2-stage double buffering.
// A-tile: register-staged (transposed store). B-tile: cp.async.
// Thread block mapping: each thread owns rows {ty*4..+3, 64+ty*4..+3} and
// cols {tx*4..+3, 64+tx*4..+3} -> all LDS.128 phases are contiguous 128B,
// bank-conflict-free (the previous tx*8 mapping had 2-way conflicts).
// ---------------------------------------------------------------------------
template<int MODE>
__global__ __launch_bounds__(256, 2)
void sgemm_kernel(const float* __restrict__ A, const float* __restrict__ W,
                  float* __restrict__ C, int M,
                  const float* __restrict__ colbias,
                  const int* __restrict__ cnt,
                  const int* __restrict__ types,
                  const float* __restrict__ type_emb)
{
    __shared__ __align__(16) float sA[2][16][128];
    __shared__ __align__(16) float sB[2][16][128];
    const int tid  = threadIdx.x;
    const int tx   = tid & 15;
    const int ty   = tid >> 4;
    const int row0 = blockIdx.y * 128;
    const int col0 = blockIdx.x * 128;

    float acc[8][8];
#pragma unroll
    for (int i = 0; i < 8; i++)
#pragma unroll
        for (int j = 0; j < 8; j++) acc[i][j] = 0.f;

    const int aRow = tid >> 2;         // 0..63
    const int aK4  = (tid & 3) << 2;   // 0,4,8,12
    const int bK   = tid >> 5;         // 0..7
    const int bN4  = (tid & 31) << 2;  // 0..124

    float4 va[2];

    // ---- prologue: stage K-tile 0 into buffer 0
#pragma unroll
    for (int rr = 0; rr < 2; rr++) {
        int gr = row0 + aRow + rr * 64;
        va[rr] = make_float4(0.f, 0.f, 0.f, 0.f);
        if (gr < M) va[rr] = *(const float4*)&A[(size_t)gr * DIM + aK4];
    }
#pragma unroll
    for (int kk = 0; kk < 2; kk++) {
        int k = bK + kk * 8;
        cp_async16(&sB[0][k][bN4], &W[(size_t)k * DIM + col0 + bN4]);
    }
    cp_async_commit();
#pragma unroll
    for (int rr = 0; rr < 2; rr++) {
        int r = aRow + rr * 64;
        sA[0][aK4 + 0][r] = va[rr].x;
        sA[0][aK4 + 1][r] = va[rr].y;
        sA[0][aK4 + 2][r] = va[rr].z;
        sA[0][aK4 + 3][r] = va[rr].w;
    }
    cp_async_wait_all();
    __syncthreads();

    const int NT = DIM / 16;  // 32 K-tiles
    for (int t = 0; t < NT; t++) {
        const int cur = t & 1;
        const int nxt = cur ^ 1;
        // ---- prefetch K-tile t+1: A -> registers, B -> smem via cp.async
        if (t + 1 < NT) {
            const int k0 = (t + 1) * 16;
#pragma unroll
            for (int rr = 0; rr < 2; rr++) {
                int gr = row0 + aRow + rr * 64;
                va[rr] = make_float4(0.f, 0.f, 0.f, 0.f);
                if (gr < M) va[rr] = *(const float4*)&A[(size_t)gr * DIM + k0 + aK4];
            }
#pragma unroll
            for (int kk = 0; kk < 2; kk++) {
                int k = bK + kk * 8;
                cp_async16(&sB[nxt][k][bN4], &W[(size_t)(k0 + k) * DIM + col0 + bN4]);
            }
            cp_async_commit();
        }
        // ---- compute on current buffer (conflict-free 16B-chunk mapping)
#pragma unroll
        for (int k = 0; k < 16; k++) {
            float4 a0 = *(const float4*)&sA[cur][k][ty * 4];
            float4 a1 = *(const float4*)&sA[cur][k][ty * 4 + 64];
            float4 b0 = *(const float4*)&sB[cur][k][tx * 4];
            float4 b1 = *(const float4*)&sB[cur][k][tx * 4 + 64];
            float ra[8] = {a0.x, a0.y, a0.z, a0.w, a1.x, a1.y, a1.z, a1.w};
            float rb[8] = {b0.x, b0.y, b0.z, b0.w, b1.x, b1.y, b1.z, b1.w};
#pragma unroll
            for (int i = 0; i < 8; i++)
#pragma unroll
                for (int j = 0; j < 8; j++)
                    acc[i][j] = fmaf(ra[i], rb[j], acc[i][j]);
        }
        // ---- stage t+1 A registers -> alternate smem buffer, drain cp.async
        if (t + 1 < NT) {
#pragma unroll
            for (int rr = 0; rr < 2; rr++) {
                int r = aRow + rr * 64;
                sA[nxt][aK4 + 0][r] = va[rr].x;
                sA[nxt][aK4 + 1][r] = va[rr].y;
                sA[nxt][aK4 + 2][r] = va[rr].z;
                sA[nxt][aK4 + 3][r] = va[rr].w;
            }
            cp_async_wait_all();
            __syncthreads();
        }
    }

    // ---- epilogue (row i: {ty*4+i} for i<4, {64+ty*4+i-4} for i>=4;
    //                col group jj: col0 + jj*64 + tx*4)
#pragma unroll
    for (int i = 0; i < 8; i++) {
        int r = row0 + ((i < 4) ? (ty * 4 + i) : (64 + ty * 4 + (i - 4)));
        if (r >= M) continue;
        float invd = 1.f, hb = 0.f;
        const float* te = nullptr;
        if (MODE == 1) {
            int cn = cnt[r];
            invd = 1.f / (float)(cn > 0 ? cn : 1);
            hb   = (cn > 0) ? 1.f : 0.f;
            te   = type_emb + (size_t)types[r] * DIM;
        }
#pragma unroll
        for (int jj = 0; jj < 2; jj++) {
            int c = col0 + jj * 64 + tx * 4;
            float4 v = make_float4(acc[i][jj * 4 + 0], acc[i][jj * 4 + 1],
                                   acc[i][jj * 4 + 2], acc[i][jj * 4 + 3]);
            if (MODE == 1) {
                v.x = v.x * invd + hb * colbias[c + 0] + te[c + 0];
                v.y = v.y * invd + hb * colbias[c + 1] + te[c + 1];
                v.z = v.z * invd + hb * colbias[c + 2] + te[c + 2];
                v.w = v.w * invd + hb * colbias[c + 3] + te[c + 3];
            } else if (MODE == 2) {
                v.x += colbias[c + 0];
                v.y += colbias[c + 1];
                v.z += colbias[c + 2];
                v.w += colbias[c + 3];
            }
            *(float4*)&C[(size_t)r * DIM + c] = v;
        }
    }
}

// ---------------------------------------------------------------------------
// Node epilogue: out = gelu(layernorm(x + nacc/deg + b2))  (one block per row)
// ---------------------------------------------------------------------------
__device__ __forceinline__ float gelu_exact(float y)
{
    return 0.5f * y * (1.f + erff(y * 0.70710678118654752440f));
}

__global__ __launch_bounds__(128)
void node_epilogue_kernel(const float* __restrict__ xin,
                          float* __restrict__ xout,
                          const float* __restrict__ b2,
                          const float* __restrict__ lng,
                          const float* __restrict__ lnb)
{
    const int n = blockIdx.x;
    const int t = threadIdx.x;
    const size_t base = (size_t)n * DIM + t * 4;
    const int cn = g_ncnt[n];
    const float invd = 1.f / (float)(cn > 0 ? cn : 1);

    float4 a  = *(const float4*)&g_nacc[base];
    float4 xi = *(const float4*)&xin[base];
    float4 bb = *(const float4*)&b2[t * 4];
    float4 v;
    v.x = fmaf(a.x, invd, bb.x) + xi.x;
    v.y = fmaf(a.y, invd, bb.y) + xi.y;
    v.z = fmaf(a.z, invd, bb.z) + xi.z;
    v.w = fmaf(a.w, invd, bb.w) + xi.w;

    float s = v.x + v.y + v.z + v.w;
    float q = v.x * v.x + v.y * v.y + v.z * v.z + v.w * v.w;
#pragma unroll
    for (int o = 16; o; o >>= 1) {
        s += __shfl_xor_sync(0xffffffffu, s, o);
        q += __shfl_xor_sync(0xffffffffu, q, o);
    }
    __shared__ float ss[4], sq[4];
    if ((t & 31) == 0) { ss[t >> 5] = s; sq[t >> 5] = q; }
    __syncthreads();
    s = ss[0] + ss[1] + ss[2] + ss[3];
    q = sq[0] + sq[1] + sq[2] + sq[3];

    const float mean = s * (1.f / 512.f);
    const float var  = q * (1.f / 512.f) - mean * mean;
    const float rstd = rsqrtf(var + 1e-5f);

    float4 gg = *(const float4*)&lng[t * 4];
    float4 lb = *(const float4*)&lnb[t * 4];
    float4 o;
    o.x = gelu_exact(fmaf((v.x - mean) * rstd, gg.x, lb.x));
    o.y = gelu_exact(fmaf((v.y - mean) * rstd, gg.y, lb.y));
    o.z = gelu_exact(fmaf((v.z - mean) * rstd, gg.z, lb.z));
    o.w = gelu_exact(fmaf((v.w - mean) * rstd, gg.w, lb.w));
    *(float4*)&xout[base] = o;
}

// ---------------------------------------------------------------------------
// Graph pooling
// ---------------------------------------------------------------------------
__global__ __launch_bounds__(128)
void pool_kernel(const float* __restrict__ xsrc, const int* __restrict__ batch)
{
    const int n = blockIdx.x;
    const int t = threadIdx.x;
    const int b = batch[n];
    float4 v = *(const float4*)&xsrc[(size_t)n * DIM + t * 4];
    red_add_v4(&g_gsum[(size_t)b * DIM + t * 4], v);
}

__global__ void gavg_kernel()
{
    int i = blockIdx.x * blockDim.x + threadIdx.x;
    if (i < NGRAPHS * DIM) {
        int g = i >> 9;
        int cn = g_gcnt[g];
        g_gavg[i] = g_gsum[i] / (float)(cn > 0 ? cn : 1);
    }
}

__global__ void batch_copy_kernel(const int* __restrict__ batch, float* __restrict__ out)
{
    int n = blockIdx.x * blockDim.x + threadIdx.x;
    if (n < NNODES) out[n] = (float)batch[n];
}

// ---------------------------------------------------------------------------
// Launch
// ---------------------------------------------------------------------------
extern "C" void kernel_launch(void* const* d_in, const int* in_sizes, int n_in,
                              void* d_out, int out_size)
{
    const float* nf        = (const float*)d_in[0];
    const int*   node_idx  = (const int*)d_in[1];
    const int*   hedge_idx = (const int*)d_in[2];
    const int*   htypes    = (const int*)d_in[3];
    const int*   batch     = (const int*)d_in[4];

    // Locate weight block robustly (optional scalar num_graphs input may be at index 5)
    int w = 5;
    for (int i = 5; i < n_in; i++) {
        if (in_sizes[i] == DIN * DIM) { w = i; break; }
    }
    const float* in_w     = (const float*)d_in[w + 0];
    const float* in_b     = (const float*)d_in[w + 1];
    const float* type_emb = (const float*)d_in[w + 2];
    const float* l1_w     = (const float*)d_in[w + 3];
    const float* l1_b     = (const float*)d_in[w + 4];
    const float* l2_w     = (const float*)d_in[w + 5];
    const float* l2_b     = (const float*)d_in[w + 6];
    const float* ln_g     = (const float*)d_in[w + 7];
    const float* ln_b     = (const float*)d_in[w + 8];
    const float* out_w    = (const float*)d_in[w + 9];
    const float* out_b    = (const float*)d_in[w + 10];

    float* out = (float*)d_out;

    // Symbol addresses (lookup only; capture-safe)
    void *pX, *pA, *pMsg, *pNacc, *pHc, *pNc, *pGc, *pGs, *pGa;
    cudaGetSymbolAddress(&pX, g_x);
    cudaGetSymbolAddress(&pA, g_A);
    cudaGetSymbolAddress(&pMsg, g_msg);
    cudaGetSymbolAddress(&pNacc, g_nacc);
    cudaGetSymbolAddress(&pHc, g_hcnt);
    cudaGetSymbolAddress(&pNc, g_ncnt);
    cudaGetSymbolAddress(&pGc, g_gcnt);
    cudaGetSymbolAddress(&pGs, g_gsum);
    cudaGetSymbolAddress(&pGa, g_gavg);

    const size_t GSZ = (size_t)NGRAPHS * DIM;           // 524288
    const size_t NSZ = (size_t)NNODES * DIM;            // 51200000
    const bool has_nodes = (size_t)out_size >= GSZ + NSZ;
    const bool has_batch = (size_t)out_size >= GSZ + NSZ + NNODES;
    float* nodes_out = has_nodes ? out + GSZ : (float*)pX;

    // Degrees (fused counts)
    cudaMemsetAsync(pHc, 0, sizeof(int) * NHEDGES, 0);
    cudaMemsetAsync(pNc, 0, sizeof(int) * NNODES, 0);
    cudaMemsetAsync(pGc, 0, sizeof(int) * NGRAPHS, 0);
    count_all_kernel<<<(NINC + 255) / 256, 256>>>(node_idx, hedge_idx, batch);

    // Input projection
    input_gemm_kernel<<<NNODES / 16, 128>>>(nf, in_w, in_b);

    const dim3 gemm_grid_h(4, (NHEDGES + 127) / 128);

    for (int i = 0; i < NLAYERS; i++) {
        // A = segment_sum(x[node_idx]) over hedges
        cudaMemsetAsync(pA, 0, sizeof(float) * NHEDGES * DIM, 0);
        spmm_kernel<<<(NINC + 1) / 2, 256>>>(node_idx, hedge_idx,
                                             (const float*)pX, (float*)pA);
        // msg = (A@W1 + cnt*b1)/clip(cnt,1) + type_emb[type]
        sgemm_kernel<1><<<gemm_grid_h, 256>>>(
            (const float*)pA, l1_w + (size_t)i * DIM * DIM, (float*)pMsg, NHEDGES,
            l1_b + (size_t)i * DIM, (const int*)pHc, htypes, type_emb);
        // B = msg @ W2   (reuse g_A)
        sgemm_kernel<0><<<gemm_grid_h, 256>>>(
            (const float*)pMsg, l2_w + (size_t)i * DIM * DIM, (float*)pA, NHEDGES,
            nullptr, nullptr, nullptr, nullptr);
        // nacc = segment_sum(B[hedge_idx]) over nodes
        cudaMemsetAsync(pNacc, 0, sizeof(float) * NSZ, 0);
        spmm_kernel<<<(NINC + 1) / 2, 256>>>(hedge_idx, node_idx,
                                             (const float*)pA, (float*)pNacc);
        // x = gelu(LN(x + nacc/deg + b2))
        float* xo = (i == NLAYERS - 1) ? nodes_out : (float*)pX;
        node_epilogue_kernel<<<NNODES, 128>>>(
            (const float*)pX, xo,
            l2_b + (size_t)i * DIM, ln_g + (size_t)i * DIM, ln_b + (size_t)i * DIM);
    }

    // Graph pooling + output projection
    cudaMemsetAsync(pGs, 0, sizeof(float) * GSZ, 0);
    pool_kernel<<<NNODES, 128>>>((const float*)nodes_out, batch);
    gavg_kernel<<<(NGRAPHS * DIM + 255) / 256, 256>>>();
    sgemm_kernel<2><<<dim3(4, NGRAPHS / 128), 256>>>(
        (const float*)pGa, out_w, out, NGRAPHS,
        out_b, nullptr, nullptr, nullptr);

    if (has_batch)
        batch_copy_kernel<<<(NNODES + 255) / 256, 256>>>(batch, out + GSZ + NSZ);
}

// round 15
// speedup vs baseline: 1.2844x; 1.1794x over previous
#include <cuda_runtime.h>
#include <math.h>

// Problem constants (fixed shapes)
#define NNODES  100000
#define NHEDGES 50000
#define NINC    300000
#define NGRAPHS 1024
#define DIN     49
#define DIM     512
#define NLAYERS 3

// ---------------------------------------------------------------------------
// Scratch (static device globals; no runtime allocation allowed)
// ---------------------------------------------------------------------------
__device__ __align__(16) float g_x[(size_t)NNODES * DIM];      // node features
__device__ __align__(16) float g_A[(size_t)NHEDGES * DIM];     // hedge aggregate / B
__device__ __align__(16) float g_msg[(size_t)NHEDGES * DIM];   // hedge_msg
__device__ int   g_hcnt[NHEDGES];
__device__ int   g_ncnt[NNODES];
__device__ int   g_gcnt[NGRAPHS];
__device__ int   g_hoff[NHEDGES];        // CSR offsets (hedge segments)
__device__ int   g_noff[NNODES];         // CSR offsets (node segments)
__device__ int   g_hcur[NHEDGES];        // scatter cursors
__device__ int   g_ncur[NNODES];
__device__ int   g_hedge_nodes[NINC];    // per-hedge list of node ids
__device__ int   g_node_hedges[NINC];    // per-node list of hedge ids
__device__ __align__(16) float g_gsum[NGRAPHS * DIM];
__device__ __align__(16) float g_gavg[NGRAPHS * DIM];

// ---------------------------------------------------------------------------
// Small PTX helpers (no external headers)
// ---------------------------------------------------------------------------
__device__ __forceinline__ void cp_async16(void* smem_dst, const void* gmem_src)
{
    unsigned s = (unsigned)__cvta_generic_to_shared(smem_dst);
    asm volatile("cp.async.cg.shared.global [%0], [%1], 16;\n" :: "r"(s), "l"(gmem_src));
}
__device__ __forceinline__ void cp_async_commit() { asm volatile("cp.async.commit_group;\n"); }
__device__ __forceinline__ void cp_async_wait_all() { asm volatile("cp.async.wait_all;\n" ::: "memory"); }

__device__ __forceinline__ void red_add_v4(float* p, float4 v)
{
#if defined(__CUDA_ARCH__) && (__CUDA_ARCH__ >= 900)
    asm volatile("red.global.add.v4.f32 [%0], {%1, %2, %3, %4};\n"
                 :: "l"(p), "f"(v.x), "f"(v.y), "f"(v.z), "f"(v.w) : "memory");
#else
    atomicAdd(p + 0, v.x);
    atomicAdd(p + 1, v.y);
    atomicAdd(p + 2, v.z);
    atomicAdd(p + 3, v.w);
#endif
}

// ---------------------------------------------------------------------------
// Degree / count kernel (fused): incidence degrees + per-graph node counts
// ---------------------------------------------------------------------------
__global__ void count_all_kernel(const int* __restrict__ node_idx,
                                 const int* __restrict__ hedge_idx,
                                 const int* __restrict__ batch)
{
    int e = blockIdx.x * blockDim.x + threadIdx.x;
    if (e < NINC) {
        atomicAdd(&g_ncnt[node_idx[e]], 1);
        atomicAdd(&g_hcnt[hedge_idx[e]], 1);
    }
    if (e < NNODES) {
        atomicAdd(&g_gcnt[batch[e]], 1);
    }
}

// ---------------------------------------------------------------------------
// Exclusive scan (single block, 1024 threads) — n up to ~100K
// ---------------------------------------------------------------------------
__global__ __launch_bounds__(1024)
void scan_kernel(const int* __restrict__ cnt, int* __restrict__ off, int n)
{
    __shared__ int part[1024];
    const int t = threadIdx.x;
    const int chunk = (n + 1023) / 1024;
    const int lo = t * chunk;
    const int hi = (lo + chunk < n) ? lo + chunk : n;

    int s = 0;
    for (int i = lo; i < hi; i++) s += cnt[i];
    part[t] = s;
    __syncthreads();
    if (t == 0) {
        int run = 0;
        for (int i = 0; i < 1024; i++) { int tmp = part[i]; part[i] = run; run += tmp; }
    }
    __syncthreads();
    int run = part[t];
    for (int i = lo; i < hi; i++) { off[i] = run; run += cnt[i]; }
}

// ---------------------------------------------------------------------------
// CSR scatter: fill adjacency lists (cursor atomics; order within segment
// is arbitrary — only affects fp sum order at ~1e-7)
// ---------------------------------------------------------------------------
__global__ void csr_fill_kernel(const int* __restrict__ node_idx,
                                const int* __restrict__ hedge_idx)
{
    int e = blockIdx.x * blockDim.x + threadIdx.x;
    if (e >= NINC) return;
    int nid = node_idx[e];
    int hid = hedge_idx[e];
    int ph = atomicAdd(&g_hcur[hid], 1);
    g_hedge_nodes[g_hoff[hid] + ph] = nid;
    int pn = atomicAdd(&g_ncur[nid], 1);
    g_node_hedges[g_noff[nid] + pn] = hid;
}

// ---------------------------------------------------------------------------
// Input GEMM: x = node_features[100000,49] @ in_w[49,512] + in_b
// ---------------------------------------------------------------------------
__global__ __launch_bounds__(128)
void input_gemm_kernel(const float* __restrict__ nf,
                       const float* __restrict__ w,
                       const float* __restrict__ b)
{
    __shared__ float snf[16 * DIN];
    const int r0 = blockIdx.x * 16;
    const int tid = threadIdx.x;
    for (int i = tid; i < 16 * DIN; i += 128)
        snf[i] = nf[(size_t)r0 * DIN + i];   // rows contiguous
    __syncthreads();

    const int c0 = tid * 4;
    float4 acc[16];
#pragma unroll
    for (int r = 0; r < 16; r++) acc[r] = make_float4(0.f, 0.f, 0.f, 0.f);

    for (int k = 0; k < DIN; k++) {
        float4 w4 = *(const float4*)&w[(size_t)k * DIM + c0];
#pragma unroll
        for (int r = 0; r < 16; r++) {
            float a = snf[r * DIN + k];
            acc[r].x = fmaf(a, w4.x, acc[r].x);
            acc[r].y = fmaf(a, w4.y, acc[r].y);
            acc[r].z = fmaf(a, w4.z, acc[r].z);
            acc[r].w = fmaf(a, w4.w, acc[r].w);
        }
    }
    float4 bb = *(const float4*)&b[c0];
#pragma unroll
    for (int r = 0; r < 16; r++) {
        float4 v = acc[r];
        v.x += bb.x; v.y += bb.y; v.z += bb.z; v.w += bb.w;
        *(float4*)&g_x[(size_t)(r0 + r) * DIM + c0] = v;
    }
}

// ---------------------------------------------------------------------------
// Hedge gather: A[h] = sum over nodes in hedge h of x[node]  (CSR, no atomics)
// One 128-thread block per hedge; thread owns 4 contiguous columns.
// ---------------------------------------------------------------------------
__global__ __launch_bounds__(128)
void hedge_gather_kernel(const float* __restrict__ x, float* __restrict__ A)
{
    const int h = blockIdx.x;
    const int c = threadIdx.x * 4;
    const int start = g_hoff[h];
    const int deg = g_hcnt[h];
    float4 acc = make_float4(0.f, 0.f, 0.f, 0.f);
    for (int j = 0; j < deg; j++) {
        int nid = g_hedge_nodes[start + j];   // broadcast load
        float4 v = *(const float4*)&x[(size_t)nid * DIM + c];
        acc.x += v.x; acc.y += v.y; acc.z += v.z; acc.w += v.w;
    }
    *(float4*)&A[(size_t)h * DIM + c] = acc;
}

// ---------------------------------------------------------------------------
// SGEMM: C[M,512] = A[M,512] @ W[512,512]  (+ per-mode epilogue)
// MODE 0: plain       MODE 1: hedge_msg epilogue    MODE 2: + column bias
// 128x128x16 tiles, 256 threads, 8x8 microtile, 2-stage double buffering.
// Conflict-free 16B-chunk mapping (measured R14: L1 67%, fma 66%).
// ---------------------------------------------------------------------------
template<int MODE>
__global__ __launch_bounds__(256, 2)
void sgemm_kernel(const float* __restrict__ A, const float* __restrict__ W,
                  float* __restrict__ C, int M,
                  const float* __restrict__ colbias,
                  const int* __restrict__ cnt,
                  const int* __restrict__ types,
                  const float* __restrict__ type_emb)
{
    __shared__ __align__(16) float sA[2][16][128];
    __shared__ __align__(16) float sB[2][16][128];
    const int tid  = threadIdx.x;
    const int tx   = tid & 15;
    const int ty   = tid >> 4;
    const int row0 = blockIdx.y * 128;
    const int col0 = blockIdx.x * 128;

    float acc[8][8];
#pragma unroll
    for (int i = 0; i < 8; i++)
#pragma unroll
        for (int j = 0; j < 8; j++) acc[i][j] = 0.f;

    const int aRow = tid >> 2;         // 0..63
    const int aK4  = (tid & 3) << 2;   // 0,4,8,12
    const int bK   = tid >> 5;         // 0..7
    const int bN4  = (tid & 31) << 2;  // 0..124

    float4 va[2];

    // ---- prologue: stage K-tile 0 into buffer 0
#pragma unroll
    for (int rr = 0; rr < 2; rr++) {
        int gr = row0 + aRow + rr * 64;
        va[rr] = make_float4(0.f, 0.f, 0.f, 0.f);
        if (gr < M) va[rr] = *(const float4*)&A[(size_t)gr * DIM + aK4];
    }
#pragma unroll
    for (int kk = 0; kk < 2; kk++) {
        int k = bK + kk * 8;
        cp_async16(&sB[0][k][bN4], &W[(size_t)k * DIM + col0 + bN4]);
    }
    cp_async_commit();
#pragma unroll
    for (int rr = 0; rr < 2; rr++) {
        int r = aRow + rr * 64;
        sA[0][aK4 + 0][r] = va[rr].x;
        sA[0][aK4 + 1][r] = va[rr].y;
        sA[0][aK4 + 2][r] = va[rr].z;
        sA[0][aK4 + 3][r] = va[rr].w;
    }
    cp_async_wait_all();
    __syncthreads();

    const int NT = DIM / 16;  // 32 K-tiles
    for (int t = 0; t < NT; t++) {
        const int cur = t & 1;
        const int nxt = cur ^ 1;
        // ---- prefetch K-tile t+1: A -> registers, B -> smem via cp.async
        if (t + 1 < NT) {
            const int k0 = (t + 1) * 16;
#pragma unroll
            for (int rr = 0; rr < 2; rr++) {
                int gr = row0 + aRow + rr * 64;
                va[rr] = make_float4(0.f, 0.f, 0.f, 0.f);
                if (gr < M) va[rr] = *(const float4*)&A[(size_t)gr * DIM + k0 + aK4];
            }
#pragma unroll
            for (int kk = 0; kk < 2; kk++) {
                int k = bK + kk * 8;
                cp_async16(&sB[nxt][k][bN4], &W[(size_t)(k0 + k) * DIM + col0 + bN4]);
            }
            cp_async_commit();
        }
        // ---- compute on current buffer (conflict-free 16B-chunk mapping)
#pragma unroll
        for (int k = 0; k < 16; k++) {
            float4 a0 = *(const float4*)&sA[cur][k][ty * 4];
            float4 a1 = *(const float4*)&sA[cur][k][ty * 4 + 64];
            float4 b0 = *(const float4*)&sB[cur][k][tx * 4];
            float4 b1 = *(const float4*)&sB[cur][k][tx * 4 + 64];
            float ra[8] = {a0.x, a0.y, a0.z, a0.w, a1.x, a1.y, a1.z, a1.w};
            float rb[8] = {b0.x, b0.y, b0.z, b0.w, b1.x, b1.y, b1.z, b1.w};
#pragma unroll
            for (int i = 0; i < 8; i++)
#pragma unroll
                for (int j = 0; j < 8; j++)
                    acc[i][j] = fmaf(ra[i], rb[j], acc[i][j]);
        }
        // ---- stage t+1 A registers -> alternate smem buffer, drain cp.async
        if (t + 1 < NT) {
#pragma unroll
            for (int rr = 0; rr < 2; rr++) {
                int r = aRow + rr * 64;
                sA[nxt][aK4 + 0][r] = va[rr].x;
                sA[nxt][aK4 + 1][r] = va[rr].y;
                sA[nxt][aK4 + 2][r] = va[rr].z;
                sA[nxt][aK4 + 3][r] = va[rr].w;
            }
            cp_async_wait_all();
            __syncthreads();
        }
    }

    // ---- epilogue (row i: {ty*4+i} for i<4, {64+ty*4+i-4} for i>=4;
    //                col group jj: col0 + jj*64 + tx*4)
#pragma unroll
    for (int i = 0; i < 8; i++) {
        int r = row0 + ((i < 4) ? (ty * 4 + i) : (64 + ty * 4 + (i - 4)));
        if (r >= M) continue;
        float invd = 1.f, hb = 0.f;
        const float* te = nullptr;
        if (MODE == 1) {
            int cn = cnt[r];
            invd = 1.f / (float)(cn > 0 ? cn : 1);
            hb   = (cn > 0) ? 1.f : 0.f;
            te   = type_emb + (size_t)types[r] * DIM;
        }
#pragma unroll
        for (int jj = 0; jj < 2; jj++) {
            int c = col0 + jj * 64 + tx * 4;
            float4 v = make_float4(acc[i][jj * 4 + 0], acc[i][jj * 4 + 1],
                                   acc[i][jj * 4 + 2], acc[i][jj * 4 + 3]);
            if (MODE == 1) {
                v.x = v.x * invd + hb * colbias[c + 0] + te[c + 0];
                v.y = v.y * invd + hb * colbias[c + 1] + te[c + 1];
                v.z = v.z * invd + hb * colbias[c + 2] + te[c + 2];
                v.w = v.w * invd + hb * colbias[c + 3] + te[c + 3];
            } else if (MODE == 2) {
                v.x += colbias[c + 0];
                v.y += colbias[c + 1];
                v.z += colbias[c + 2];
                v.w += colbias[c + 3];
            }
            *(float4*)&C[(size_t)r * DIM + c] = v;
        }
    }
}

// ---------------------------------------------------------------------------
// Fused node gather + epilogue: out = gelu(LN(x + (sum_h B[h])/deg + b2))
// One 128-thread block per node; CSR gather replaces g_nacc entirely.
// ---------------------------------------------------------------------------
__device__ __forceinline__ float gelu_exact(float y)
{
    return 0.5f * y * (1.f + erff(y * 0.70710678118654752440f));
}

__global__ __launch_bounds__(128)
void node_epilogue_kernel(const float* __restrict__ xin,
                          const float* __restrict__ B,
                          float* __restrict__ xout,
                          const float* __restrict__ b2,
                          const float* __restrict__ lng,
                          const float* __restrict__ lnb)
{
    const int n = blockIdx.x;
    const int t = threadIdx.x;
    const size_t base = (size_t)n * DIM + t * 4;
    const int cn = g_ncnt[n];
    const float invd = 1.f / (float)(cn > 0 ? cn : 1);
    const int start = g_noff[n];

    // CSR gather-sum of B rows
    float4 a = make_float4(0.f, 0.f, 0.f, 0.f);
    for (int j = 0; j < cn; j++) {
        int hid = g_node_hedges[start + j];   // broadcast load
        float4 v = *(const float4*)&B[(size_t)hid * DIM + t * 4];
        a.x += v.x; a.y += v.y; a.z += v.z; a.w += v.w;
    }

    float4 xi = *(const float4*)&xin[base];
    float4 bb = *(const float4*)&b2[t * 4];
    float4 v;
    v.x = fmaf(a.x, invd, bb.x) + xi.x;
    v.y = fmaf(a.y, invd, bb.y) + xi.y;
    v.z = fmaf(a.z, invd, bb.z) + xi.z;
    v.w = fmaf(a.w, invd, bb.w) + xi.w;

    float s = v.x + v.y + v.z + v.w;
    float q = v.x * v.x + v.y * v.y + v.z * v.z + v.w * v.w;
#pragma unroll
    for (int o = 16; o; o >>= 1) {
        s += __shfl_xor_sync(0xffffffffu, s, o);
        q += __shfl_xor_sync(0xffffffffu, q, o);
    }
    __shared__ float ss[4], sq[4];
    if ((t & 31) == 0) { ss[t >> 5] = s; sq[t >> 5] = q; }
    __syncthreads();
    s = ss[0] + ss[1] + ss[2] + ss[3];
    q = sq[0] + sq[1] + sq[2] + sq[3];

    const float mean = s * (1.f / 512.f);
    const float var  = q * (1.f / 512.f) - mean * mean;
    const float rstd = rsqrtf(var + 1e-5f);

    float4 gg = *(const float4*)&lng[t * 4];
    float4 lb = *(const float4*)&lnb[t * 4];
    float4 o;
    o.x = gelu_exact(fmaf((v.x - mean) * rstd, gg.x, lb.x));
    o.y = gelu_exact(fmaf((v.y - mean) * rstd, gg.y, lb.y));
    o.z = gelu_exact(fmaf((v.z - mean) * rstd, gg.z, lb.z));
    o.w = gelu_exact(fmaf((v.w - mean) * rstd, gg.w, lb.w));
    *(float4*)&xout[base] = o;
}

// ---------------------------------------------------------------------------
// Graph pooling
// ---------------------------------------------------------------------------
__global__ __launch_bounds__(128)
void pool_kernel(const float* __restrict__ xsrc, const int* __restrict__ batch)
{
    const int n = blockIdx.x;
    const int t = threadIdx.x;
    const int b = batch[n];
    float4 v = *(const float4*)&xsrc[(size_t)n * DIM + t * 4];
    red_add_v4(&g_gsum[(size_t)b * DIM + t * 4], v);
}

__global__ void gavg_kernel()
{
    int i = blockIdx.x * blockDim.x + threadIdx.x;
    if (i < NGRAPHS * DIM) {
        int g = i >> 9;
        int cn = g_gcnt[g];
        g_gavg[i] = g_gsum[i] / (float)(cn > 0 ? cn : 1);
    }
}

__global__ void batch_copy_kernel(const int* __restrict__ batch, float* __restrict__ out)
{
    int n = blockIdx.x * blockDim.x + threadIdx.x;
    if (n < NNODES) out[n] = (float)batch[n];
}

// ---------------------------------------------------------------------------
// Launch
// ---------------------------------------------------------------------------
extern "C" void kernel_launch(void* const* d_in, const int* in_sizes, int n_in,
                              void* d_out, int out_size)
{
    const float* nf        = (const float*)d_in[0];
    const int*   node_idx  = (const int*)d_in[1];
    const int*   hedge_idx = (const int*)d_in[2];
    const int*   htypes    = (const int*)d_in[3];
    const int*   batch     = (const int*)d_in[4];

    // Locate weight block robustly (optional scalar num_graphs input may be at index 5)
    int w = 5;
    for (int i = 5; i < n_in; i++) {
        if (in_sizes[i] == DIN * DIM) { w = i; break; }
    }
    const float* in_w     = (const float*)d_in[w + 0];
    const float* in_b     = (const float*)d_in[w + 1];
    const float* type_emb = (const float*)d_in[w + 2];
    const float* l1_w     = (const float*)d_in[w + 3];
    const float* l1_b     = (const float*)d_in[w + 4];
    const float* l2_w     = (const float*)d_in[w + 5];
    const float* l2_b     = (const float*)d_in[w + 6];
    const float* ln_g     = (const float*)d_in[w + 7];
    const float* ln_b     = (const float*)d_in[w + 8];
    const float* out_w    = (const float*)d_in[w + 9];
    const float* out_b    = (const float*)d_in[w + 10];

    float* out = (float*)d_out;

    // Symbol addresses (lookup only; capture-safe)
    void *pX, *pA, *pMsg, *pHc, *pNc, *pGc, *pGs, *pGa;
    void *pHoff, *pNoff, *pHcur, *pNcur;
    cudaGetSymbolAddress(&pX, g_x);
    cudaGetSymbolAddress(&pA, g_A);
    cudaGetSymbolAddress(&pMsg, g_msg);
    cudaGetSymbolAddress(&pHc, g_hcnt);
    cudaGetSymbolAddress(&pNc, g_ncnt);
    cudaGetSymbolAddress(&pGc, g_gcnt);
    cudaGetSymbolAddress(&pGs, g_gsum);
    cudaGetSymbolAddress(&pGa, g_gavg);
    cudaGetSymbolAddress(&pHoff, g_hoff);
    cudaGetSymbolAddress(&pNoff, g_noff);
    cudaGetSymbolAddress(&pHcur, g_hcur);
    cudaGetSymbolAddress(&pNcur, g_ncur);

    const size_t GSZ = (size_t)NGRAPHS * DIM;           // 524288
    const size_t NSZ = (size_t)NNODES * DIM;            // 51200000
    const bool has_nodes = (size_t)out_size >= GSZ + NSZ;
    const bool has_batch = (size_t)out_size >= GSZ + NSZ + NNODES;
    float* nodes_out = has_nodes ? out + GSZ : (float*)pX;

    // Degrees + CSR build
    cudaMemsetAsync(pHc, 0, sizeof(int) * NHEDGES, 0);
    cudaMemsetAsync(pNc, 0, sizeof(int) * NNODES, 0);
    cudaMemsetAsync(pGc, 0, sizeof(int) * NGRAPHS, 0);
    count_all_kernel<<<(NINC + 255) / 256, 256>>>(node_idx, hedge_idx, batch);
    scan_kernel<<<1, 1024>>>((const int*)pHc, (int*)pHoff, NHEDGES);
    scan_kernel<<<1, 1024>>>((const int*)pNc, (int*)pNoff, NNODES);
    cudaMemsetAsync(pHcur, 0, sizeof(int) * NHEDGES, 0);
    cudaMemsetAsync(pNcur, 0, sizeof(int) * NNODES, 0);
    csr_fill_kernel<<<(NINC + 255) / 256, 256>>>(node_idx, hedge_idx);

    // Input projection
    input_gemm_kernel<<<NNODES / 16, 128>>>(nf, in_w, in_b);

    const dim3 gemm_grid_h(4, (NHEDGES + 127) / 128);

    for (int i = 0; i < NLAYERS; i++) {
        // A[h] = sum of x rows in hedge h (CSR gather, no atomics/memset)
        hedge_gather_kernel<<<NHEDGES, 128>>>((const float*)pX, (float*)pA);
        // msg = (A@W1 + cnt*b1)/clip(cnt,1) + type_emb[type]
        sgemm_kernel<1><<<gemm_grid_h, 256>>>(
            (const float*)pA, l1_w + (size_t)i * DIM * DIM, (float*)pMsg, NHEDGES,
            l1_b + (size_t)i * DIM, (const int*)pHc, htypes, type_emb);
        // B = msg @ W2   (reuse g_A)
        sgemm_kernel<0><<<gemm_grid_h, 256>>>(
            (const float*)pMsg, l2_w + (size_t)i * DIM * DIM, (float*)pA, NHEDGES,
            nullptr, nullptr, nullptr, nullptr);
        // x = gelu(LN(x + csr_gather(B)/deg + b2))   (fused gather+epilogue)
        float* xo = (i == NLAYERS - 1) ? nodes_out : (float*)pX;
        node_epilogue_kernel<<<NNODES, 128>>>(
            (const float*)pX, (const float*)pA, xo,
            l2_b + (size_t)i * DIM, ln_g + (size_t)i * DIM, ln_b + (size_t)i * DIM);
    }

    // Graph pooling + output projection
    cudaMemsetAsync(pGs, 0, sizeof(float) * GSZ, 0);
    pool_kernel<<<NNODES, 128>>>((const float*)nodes_out, batch);
    gavg_kernel<<<(NGRAPHS * DIM + 255) / 256, 256>>>();
    sgemm_kernel<2><<<dim3(4, NGRAPHS / 128), 256>>>(
        (const float*)pGa, out_w, out, NGRAPHS,
        out_b, nullptr, nullptr, nullptr);

    if (has_batch)
        batch_copy_kernel<<<(NNODES + 255) / 256, 256>>>(batch, out + GSZ + NSZ);
}

// round 16
// speedup vs baseline: 1.3571x; 1.0566x over previous
#include <cuda_runtime.h>
#include <math.h>

// Problem constants (fixed shapes)
#define NNODES  100000
#define NHEDGES 50000
#define NINC    300000
#define NGRAPHS 1024
#define DIN     49
#define DIM     512
#define NLAYERS 3

// ---------------------------------------------------------------------------
// Scratch (static device globals; no runtime allocation allowed)
// ---------------------------------------------------------------------------
__device__ __align__(16) float g_x[(size_t)NNODES * DIM];      // node features
__device__ __align__(16) float g_A[(size_t)NHEDGES * DIM];     // hedge aggregate / B
__device__ __align__(16) float g_msg[(size_t)NHEDGES * DIM];   // hedge_msg
__device__ int   g_hcnt[NHEDGES];
__device__ int   g_ncnt[NNODES];
__device__ int   g_gcnt[NGRAPHS];
__device__ int   g_hoff[NHEDGES];        // CSR offsets (hedge segments)
__device__ int   g_noff[NNODES];         // CSR offsets (node segments)
__device__ int   g_hcur[NHEDGES];        // scatter cursors
__device__ int   g_ncur[NNODES];
__device__ int   g_hedge_nodes[NINC];    // per-hedge list of node ids
__device__ int   g_node_hedges[NINC];    // per-node list of hedge ids
__device__ __align__(16) float g_gsum[NGRAPHS * DIM];
__device__ __align__(16) float g_gavg[NGRAPHS * DIM];

// ---------------------------------------------------------------------------
// Small PTX helpers (no external headers)
// ---------------------------------------------------------------------------
__device__ __forceinline__ void cp_async16(void* smem_dst, const void* gmem_src)
{
    unsigned s = (unsigned)__cvta_generic_to_shared(smem_dst);
    asm volatile("cp.async.cg.shared.global [%0], [%1], 16;\n" :: "r"(s), "l"(gmem_src));
}
__device__ __forceinline__ void cp_async_commit() { asm volatile("cp.async.commit_group;\n"); }
__device__ __forceinline__ void cp_async_wait_all() { asm volatile("cp.async.wait_all;\n" ::: "memory"); }

__device__ __forceinline__ void red_add_v4(float* p, float4 v)
{
#if defined(__CUDA_ARCH__) && (__CUDA_ARCH__ >= 900)
    asm volatile("red.global.add.v4.f32 [%0], {%1, %2, %3, %4};\n"
                 :: "l"(p), "f"(v.x), "f"(v.y), "f"(v.z), "f"(v.w) : "memory");
#else
    atomicAdd(p + 0, v.x);
    atomicAdd(p + 1, v.y);
    atomicAdd(p + 2, v.z);
    atomicAdd(p + 3, v.w);
#endif
}

__device__ __forceinline__ unsigned tf32_of(float x)
{
    unsigned r;
    asm("cvt.rna.tf32.f32 %0, %1;" : "=r"(r) : "f"(x));
    return r;
}

#define MMA8(d, a0, a1, a2, a3, b0, b1) \
    asm volatile("mma.sync.aligned.m16n8k8.row.col.f32.tf32.tf32.f32 " \
        "{%0,%1,%2,%3},{%4,%5,%6,%7},{%8,%9},{%0,%1,%2,%3};" \
        : "+f"((d)[0]), "+f"((d)[1]), "+f"((d)[2]), "+f"((d)[3]) \
        : "r"(a0), "r"(a1), "r"(a2), "r"(a3), "r"(b0), "r"(b1))

// ---------------------------------------------------------------------------
// Degree / count kernel (fused): incidence degrees + per-graph node counts
// ---------------------------------------------------------------------------
__global__ void count_all_kernel(const int* __restrict__ node_idx,
                                 const int* __restrict__ hedge_idx,
                                 const int* __restrict__ batch)
{
    int e = blockIdx.x * blockDim.x + threadIdx.x;
    if (e < NINC) {
        atomicAdd(&g_ncnt[node_idx[e]], 1);
        atomicAdd(&g_hcnt[hedge_idx[e]], 1);
    }
    if (e < NNODES) {
        atomicAdd(&g_gcnt[batch[e]], 1);
    }
}

// ---------------------------------------------------------------------------
// Exclusive scan (single block, 1024 threads) — n up to ~100K
// ---------------------------------------------------------------------------
__global__ __launch_bounds__(1024)
void scan_kernel(const int* __restrict__ cnt, int* __restrict__ off, int n)
{
    __shared__ int part[1024];
    const int t = threadIdx.x;
    const int chunk = (n + 1023) / 1024;
    const int lo = t * chunk;
    const int hi = (lo + chunk < n) ? lo + chunk : n;

    int s = 0;
    for (int i = lo; i < hi; i++) s += cnt[i];
    part[t] = s;
    __syncthreads();
    if (t == 0) {
        int run = 0;
        for (int i = 0; i < 1024; i++) { int tmp = part[i]; part[i] = run; run += tmp; }
    }
    __syncthreads();
    int run = part[t];
    for (int i = lo; i < hi; i++) { off[i] = run; run += cnt[i]; }
}

// ---------------------------------------------------------------------------
// CSR scatter: fill adjacency lists (cursor atomics)
// ---------------------------------------------------------------------------
__global__ void csr_fill_kernel(const int* __restrict__ node_idx,
                                const int* __restrict__ hedge_idx)
{
    int e = blockIdx.x * blockDim.x + threadIdx.x;
    if (e >= NINC) return;
    int nid = node_idx[e];
    int hid = hedge_idx[e];
    int ph = atomicAdd(&g_hcur[hid], 1);
    g_hedge_nodes[g_hoff[hid] + ph] = nid;
    int pn = atomicAdd(&g_ncur[nid], 1);
    g_node_hedges[g_noff[nid] + pn] = hid;
}

// ---------------------------------------------------------------------------
// Input GEMM: x = node_features[100000,49] @ in_w[49,512] + in_b
// ---------------------------------------------------------------------------
__global__ __launch_bounds__(128)
void input_gemm_kernel(const float* __restrict__ nf,
                       const float* __restrict__ w,
                       const float* __restrict__ b)
{
    __shared__ float snf[16 * DIN];
    const int r0 = blockIdx.x * 16;
    const int tid = threadIdx.x;
    for (int i = tid; i < 16 * DIN; i += 128)
        snf[i] = nf[(size_t)r0 * DIN + i];   // rows contiguous
    __syncthreads();

    const int c0 = tid * 4;
    float4 acc[16];
#pragma unroll
    for (int r = 0; r < 16; r++) acc[r] = make_float4(0.f, 0.f, 0.f, 0.f);

    for (int k = 0; k < DIN; k++) {
        float4 w4 = *(const float4*)&w[(size_t)k * DIM + c0];
#pragma unroll
        for (int r = 0; r < 16; r++) {
            float a = snf[r * DIN + k];
            acc[r].x = fmaf(a, w4.x, acc[r].x);
            acc[r].y = fmaf(a, w4.y, acc[r].y);
            acc[r].z = fmaf(a, w4.z, acc[r].z);
            acc[r].w = fmaf(a, w4.w, acc[r].w);
        }
    }
    float4 bb = *(const float4*)&b[c0];
#pragma unroll
    for (int r = 0; r < 16; r++) {
        float4 v = acc[r];
        v.x += bb.x; v.y += bb.y; v.z += bb.z; v.w += bb.w;
        *(float4*)&g_x[(size_t)(r0 + r) * DIM + c0] = v;
    }
}

// ---------------------------------------------------------------------------
// Hedge gather: A[h] = sum over nodes in hedge h of x[node]  (CSR, no atomics)
// ---------------------------------------------------------------------------
__global__ __launch_bounds__(128)
void hedge_gather_kernel(const float* __restrict__ x, float* __restrict__ A)
{
    const int h = blockIdx.x;
    const int c = threadIdx.x * 4;
    const int start = g_hoff[h];
    const int deg = g_hcnt[h];
    float4 acc = make_float4(0.f, 0.f, 0.f, 0.f);
    for (int j = 0; j < deg; j++) {
        int nid = g_hedge_nodes[start + j];   // broadcast load
        float4 v = *(const float4*)&x[(size_t)nid * DIM + c];
        acc.x += v.x; acc.y += v.y; acc.z += v.z; acc.w += v.w;
    }
    *(float4*)&A[(size_t)h * DIM + c] = acc;
}

// ---------------------------------------------------------------------------
// SGEMM via split-TF32 tensor cores: C[M,512] = A[M,512] @ W[512,512]
// MODE 0: plain   MODE 1: hedge_msg epilogue   MODE 2: + column bias
// 128x128 tile, KT=8, 256 threads = 8 warps (4Mx2N), warp tile 32x64.
// A: register-staged, split into tf32 hi/lo, stored PRE-PERMUTED into
//    mma fragment layout [sm][lane][reg] -> fragment load = one LDS.128.
// B: cp.async into [k][136]-padded rows -> fragment LDS.32 conflict-free.
// D = Ah*Bh + Ah*Bl + Al*Bh  (split-tf32, ~1e-6 accuracy).
// ---------------------------------------------------------------------------
template<int MODE>
__global__ __launch_bounds__(256, 2)
void sgemm_kernel(const float* __restrict__ A, const float* __restrict__ W,
                  float* __restrict__ C, int M,
                  const float* __restrict__ colbias,
                  const int* __restrict__ cnt,
                  const int* __restrict__ types,
                  const float* __restrict__ type_emb)
{
    __shared__ __align__(16) float sAh[2][8][32][4];
    __shared__ __align__(16) float sAl[2][8][32][4];
    __shared__ __align__(16) float sB[2][8][136];

    const int tid  = threadIdx.x;
    const int lane = tid & 31;
    const int wid  = tid >> 5;           // 0..7
    const int wm   = wid & 3;            // warp row group
    const int wn0  = (wid >> 2) * 64;    // warp col base
    const int g    = lane >> 2;
    const int t4   = lane & 3;
    const int row0 = blockIdx.y * 128;
    const int col0 = blockIdx.x * 128;

    // A staging: thread owns row am, k-half ak4
    const int am   = tid >> 1;            // 0..127
    const int ak4  = (tid & 1) * 4;       // 0 or 4
    const int asub = am >> 4;             // subtile 0..7
    const int alan = (am & 7) * 4;        // lane base (j added)
    const int aidx = (tid & 1) * 2 + ((am >> 3) & 1);  // fragment reg index
    // B staging
    const int bk  = tid >> 5;             // 0..7
    const int bn4 = (tid & 31) * 4;       // 0..124

    float acc[2][8][4];
#pragma unroll
    for (int s = 0; s < 2; s++)
#pragma unroll
        for (int nt = 0; nt < 8; nt++)
#pragma unroll
            for (int r = 0; r < 4; r++) acc[s][nt][r] = 0.f;

    float4 va;

    // ---- prologue: stage K-tile 0
    {
        int gr = row0 + am;
        va = (gr < M) ? *(const float4*)&A[(size_t)gr * DIM + ak4]
                      : make_float4(0.f, 0.f, 0.f, 0.f);
        cp_async16(&sB[0][bk][bn4], &W[(size_t)bk * DIM + col0 + bn4]);
        cp_async_commit();
        float xs[4] = {va.x, va.y, va.z, va.w};
#pragma unroll
        for (int j = 0; j < 4; j++) {
            unsigned h = tf32_of(xs[j]);
            unsigned l = tf32_of(xs[j] - __uint_as_float(h));
            sAh[0][asub][alan + j][aidx] = __uint_as_float(h);
            sAl[0][asub][alan + j][aidx] = __uint_as_float(l);
        }
        cp_async_wait_all();
        __syncthreads();
    }

    const int NT = DIM / 8;   // 64 K-tiles
    for (int tt = 0; tt < NT; tt++) {
        const int cur = tt & 1;
        const int nxt = cur ^ 1;
        // ---- prefetch tile tt+1
        if (tt + 1 < NT) {
            const int k0 = (tt + 1) * 8;
            int gr = row0 + am;
            va = (gr < M) ? *(const float4*)&A[(size_t)gr * DIM + k0 + ak4]
                          : make_float4(0.f, 0.f, 0.f, 0.f);
            cp_async16(&sB[nxt][bk][bn4], &W[(size_t)(k0 + bk) * DIM + col0 + bn4]);
            cp_async_commit();
        }
        // ---- A fragments: one LDS.128 each (pre-permuted layout)
        float4 fh0 = *(const float4*)&sAh[cur][wm * 2 + 0][lane][0];
        float4 fh1 = *(const float4*)&sAh[cur][wm * 2 + 1][lane][0];
        float4 fl0 = *(const float4*)&sAl[cur][wm * 2 + 0][lane][0];
        float4 fl1 = *(const float4*)&sAl[cur][wm * 2 + 1][lane][0];
        unsigned ah0[4] = {__float_as_uint(fh0.x), __float_as_uint(fh0.y),
                           __float_as_uint(fh0.z), __float_as_uint(fh0.w)};
        unsigned ah1[4] = {__float_as_uint(fh1.x), __float_as_uint(fh1.y),
                           __float_as_uint(fh1.z), __float_as_uint(fh1.w)};
        unsigned al0[4] = {__float_as_uint(fl0.x), __float_as_uint(fl0.y),
                           __float_as_uint(fl0.z), __float_as_uint(fl0.w)};
        unsigned al1[4] = {__float_as_uint(fl1.x), __float_as_uint(fl1.y),
                           __float_as_uint(fl1.z), __float_as_uint(fl1.w)};
#pragma unroll
        for (int nt = 0; nt < 8; nt++) {
            float b0 = sB[cur][t4][wn0 + nt * 8 + g];
            float b1 = sB[cur][t4 + 4][wn0 + nt * 8 + g];
            unsigned bh0 = tf32_of(b0);
            unsigned bl0 = tf32_of(b0 - __uint_as_float(bh0));
            unsigned bh1 = tf32_of(b1);
            unsigned bl1 = tf32_of(b1 - __uint_as_float(bh1));
            MMA8(acc[0][nt], ah0[0], ah0[1], ah0[2], ah0[3], bh0, bh1);
            MMA8(acc[0][nt], ah0[0], ah0[1], ah0[2], ah0[3], bl0, bl1);
            MMA8(acc[0][nt], al0[0], al0[1], al0[2], al0[3], bh0, bh1);
            MMA8(acc[1][nt], ah1[0], ah1[1], ah1[2], ah1[3], bh0, bh1);
            MMA8(acc[1][nt], ah1[0], ah1[1], ah1[2], ah1[3], bl0, bl1);
            MMA8(acc[1][nt], al1[0], al1[1], al1[2], al1[3], bh0, bh1);
        }
        // ---- store staged tile tt+1, sync
        if (tt + 1 < NT) {
            float xs[4] = {va.x, va.y, va.z, va.w};
#pragma unroll
            for (int j = 0; j < 4; j++) {
                unsigned h = tf32_of(xs[j]);
                unsigned l = tf32_of(xs[j] - __uint_as_float(h));
                sAh[nxt][asub][alan + j][aidx] = __uint_as_float(h);
                sAl[nxt][asub][alan + j][aidx] = __uint_as_float(l);
            }
            cp_async_wait_all();
            __syncthreads();
        }
    }

    // ---- epilogue: lane (g,t4) owns rows {wm*32+s*16+g+r8*8}, cols {nt*8+t4*2,+1}
#pragma unroll
    for (int s = 0; s < 2; s++) {
#pragma unroll
        for (int r8 = 0; r8 < 2; r8++) {
            int r = row0 + wm * 32 + s * 16 + g + r8 * 8;
            if (r >= M) continue;
            float invd = 1.f, hb = 0.f;
            const float* te = nullptr;
            if (MODE == 1) {
                int cn = cnt[r];
                invd = 1.f / (float)(cn > 0 ? cn : 1);
                hb   = (cn > 0) ? 1.f : 0.f;
                te   = type_emb + (size_t)types[r] * DIM;
            }
#pragma unroll
            for (int nt = 0; nt < 8; nt++) {
                int c = col0 + wn0 + nt * 8 + t4 * 2;
                float v0 = acc[s][nt][r8 * 2 + 0];
                float v1 = acc[s][nt][r8 * 2 + 1];
                if (MODE == 1) {
                    v0 = v0 * invd + hb * colbias[c + 0] + te[c + 0];
                    v1 = v1 * invd + hb * colbias[c + 1] + te[c + 1];
                } else if (MODE == 2) {
                    v0 += colbias[c + 0];
                    v1 += colbias[c + 1];
                }
                *(float2*)&C[(size_t)r * DIM + c] = make_float2(v0, v1);
            }
        }
    }
}

// ---------------------------------------------------------------------------
// Fused node gather + epilogue: out = gelu(LN(x + (sum_h B[h])/deg + b2))
// ---------------------------------------------------------------------------
__device__ __forceinline__ float gelu_exact(float y)
{
    return 0.5f * y * (1.f + erff(y * 0.70710678118654752440f));
}

__global__ __launch_bounds__(128)
void node_epilogue_kernel(const float* __restrict__ xin,
                          const float* __restrict__ B,
                          float* __restrict__ xout,
                          const float* __restrict__ b2,
                          const float* __restrict__ lng,
                          const float* __restrict__ lnb)
{
    const int n = blockIdx.x;
    const int t = threadIdx.x;
    const size_t base = (size_t)n * DIM + t * 4;
    const int cn = g_ncnt[n];
    const float invd = 1.f / (float)(cn > 0 ? cn : 1);
    const int start = g_noff[n];

    float4 a = make_float4(0.f, 0.f, 0.f, 0.f);
    for (int j = 0; j < cn; j++) {
        int hid = g_node_hedges[start + j];
        float4 v = *(const float4*)&B[(size_t)hid * DIM + t * 4];
        a.x += v.x; a.y += v.y; a.z += v.z; a.w += v.w;
    }

    float4 xi = *(const float4*)&xin[base];
    float4 bb = *(const float4*)&b2[t * 4];
    float4 v;
    v.x = fmaf(a.x, invd, bb.x) + xi.x;
    v.y = fmaf(a.y, invd, bb.y) + xi.y;
    v.z = fmaf(a.z, invd, bb.z) + xi.z;
    v.w = fmaf(a.w, invd, bb.w) + xi.w;

    float s = v.x + v.y + v.z + v.w;
    float q = v.x * v.x + v.y * v.y + v.z * v.z + v.w * v.w;
#pragma unroll
    for (int o = 16; o; o >>= 1) {
        s += __shfl_xor_sync(0xffffffffu, s, o);
        q += __shfl_xor_sync(0xffffffffu, q, o);
    }
    __shared__ float ss[4], sq[4];
    if ((t & 31) == 0) { ss[t >> 5] = s; sq[t >> 5] = q; }
    __syncthreads();
    s = ss[0] + ss[1] + ss[2] + ss[3];
    q = sq[0] + sq[1] + sq[2] + sq[3];

    const float mean = s * (1.f / 512.f);
    const float var  = q * (1.f / 512.f) - mean * mean;
    const float rstd = rsqrtf(var + 1e-5f);

    float4 gg = *(const float4*)&lng[t * 4];
    float4 lb = *(const float4*)&lnb[t * 4];
    float4 o;
    o.x = gelu_exact(fmaf((v.x - mean) * rstd, gg.x, lb.x));
    o.y = gelu_exact(fmaf((v.y - mean) * rstd, gg.y, lb.y));
    o.z = gelu_exact(fmaf((v.z - mean) * rstd, gg.z, lb.z));
    o.w = gelu_exact(fmaf((v.w - mean) * rstd, gg.w, lb.w));
    *(float4*)&xout[base] = o;
}

// ---------------------------------------------------------------------------
// Graph pooling
// ---------------------------------------------------------------------------
__global__ __launch_bounds__(128)
void pool_kernel(const float* __restrict__ xsrc, const int* __restrict__ batch)
{
    const int n = blockIdx.x;
    const int t = threadIdx.x;
    const int b = batch[n];
    float4 v = *(const float4*)&xsrc[(size_t)n * DIM + t * 4];
    red_add_v4(&g_gsum[(size_t)b * DIM + t * 4], v);
}

__global__ void gavg_kernel()
{
    int i = blockIdx.x * blockDim.x + threadIdx.x;
    if (i < NGRAPHS * DIM) {
        int g = i >> 9;
        int cn = g_gcnt[g];
        g_gavg[i] = g_gsum[i] / (float)(cn > 0 ? cn : 1);
    }
}

__global__ void batch_copy_kernel(const int* __restrict__ batch, float* __restrict__ out)
{
    int n = blockIdx.x * blockDim.x + threadIdx.x;
    if (n < NNODES) out[n] = (float)batch[n];
}

// ---------------------------------------------------------------------------
// Launch
// ---------------------------------------------------------------------------
extern "C" void kernel_launch(void* const* d_in, const int* in_sizes, int n_in,
                              void* d_out, int out_size)
{
    const float* nf        = (const float*)d_in[0];
    const int*   node_idx  = (const int*)d_in[1];
    const int*   hedge_idx = (const int*)d_in[2];
    const int*   htypes    = (const int*)d_in[3];
    const int*   batch     = (const int*)d_in[4];

    // Locate weight block robustly (optional scalar num_graphs input may be at index 5)
    int w = 5;
    for (int i = 5; i < n_in; i++) {
        if (in_sizes[i] == DIN * DIM) { w = i; break; }
    }
    const float* in_w     = (const float*)d_in[w + 0];
    const float* in_b     = (const float*)d_in[w + 1];
    const float* type_emb = (const float*)d_in[w + 2];
    const float* l1_w     = (const float*)d_in[w + 3];
    const float* l1_b     = (const float*)d_in[w + 4];
    const float* l2_w     = (const float*)d_in[w + 5];
    const float* l2_b     = (const float*)d_in[w + 6];
    const float* ln_g     = (const float*)d_in[w + 7];
    const float* ln_b     = (const float*)d_in[w + 8];
    const float* out_w    = (const float*)d_in[w + 9];
    const float* out_b    = (const float*)d_in[w + 10];

    float* out = (float*)d_out;

    // Symbol addresses (lookup only; capture-safe)
    void *pX, *pA, *pMsg, *pHc, *pNc, *pGc, *pGs, *pGa;
    void *pHoff, *pNoff, *pHcur, *pNcur;
    cudaGetSymbolAddress(&pX, g_x);
    cudaGetSymbolAddress(&pA, g_A);
    cudaGetSymbolAddress(&pMsg, g_msg);
    cudaGetSymbolAddress(&pHc, g_hcnt);
    cudaGetSymbolAddress(&pNc, g_ncnt);
    cudaGetSymbolAddress(&pGc, g_gcnt);
    cudaGetSymbolAddress(&pGs, g_gsum);
    cudaGetSymbolAddress(&pGa, g_gavg);
    cudaGetSymbolAddress(&pHoff, g_hoff);
    cudaGetSymbolAddress(&pNoff, g_noff);
    cudaGetSymbolAddress(&pHcur, g_hcur);
    cudaGetSymbolAddress(&pNcur, g_ncur);

    const size_t GSZ = (size_t)NGRAPHS * DIM;           // 524288
    const size_t NSZ = (size_t)NNODES * DIM;            // 51200000
    const bool has_nodes = (size_t)out_size >= GSZ + NSZ;
    const bool has_batch = (size_t)out_size >= GSZ + NSZ + NNODES;
    float* nodes_out = has_nodes ? out + GSZ : (float*)pX;

    // Degrees + CSR build
    cudaMemsetAsync(pHc, 0, sizeof(int) * NHEDGES, 0);
    cudaMemsetAsync(pNc, 0, sizeof(int) * NNODES, 0);
    cudaMemsetAsync(pGc, 0, sizeof(int) * NGRAPHS, 0);
    count_all_kernel<<<(NINC + 255) / 256, 256>>>(node_idx, hedge_idx, batch);
    scan_kernel<<<1, 1024>>>((const int*)pHc, (int*)pHoff, NHEDGES);
    scan_kernel<<<1, 1024>>>((const int*)pNc, (int*)pNoff, NNODES);
    cudaMemsetAsync(pHcur, 0, sizeof(int) * NHEDGES, 0);
    cudaMemsetAsync(pNcur, 0, sizeof(int) * NNODES, 0);
    csr_fill_kernel<<<(NINC + 255) / 256, 256>>>(node_idx, hedge_idx);

    // Input projection
    input_gemm_kernel<<<NNODES / 16, 128>>>(nf, in_w, in_b);

    const dim3 gemm_grid_h(4, (NHEDGES + 127) / 128);

    for (int i = 0; i < NLAYERS; i++) {
        // A[h] = sum of x rows in hedge h (CSR gather, no atomics/memset)
        hedge_gather_kernel<<<NHEDGES, 128>>>((const float*)pX, (float*)pA);
        // msg = (A@W1 + cnt*b1)/clip(cnt,1) + type_emb[type]
        sgemm_kernel<1><<<gemm_grid_h, 256>>>(
            (const float*)pA, l1_w + (size_t)i * DIM * DIM, (float*)pMsg, NHEDGES,
            l1_b + (size_t)i * DIM, (const int*)pHc, htypes, type_emb);
        // B = msg @ W2   (reuse g_A)
        sgemm_kernel<0><<<gemm_grid_h, 256>>>(
            (const float*)pMsg, l2_w + (size_t)i * DIM * DIM, (float*)pA, NHEDGES,
            nullptr, nullptr, nullptr, nullptr);
        // x = gelu(LN(x + csr_gather(B)/deg + b2))   (fused gather+epilogue)
        float* xo = (i == NLAYERS - 1) ? nodes_out : (float*)pX;
        node_epilogue_kernel<<<NNODES, 128>>>(
            (const float*)pX, (const float*)pA, xo,
            l2_b + (size_t)i * DIM, ln_g + (size_t)i * DIM, ln_b + (size_t)i * DIM);
    }

    // Graph pooling + output projection
    cudaMemsetAsync(pGs, 0, sizeof(float) * GSZ, 0);
    pool_kernel<<<NNODES, 128>>>((const float*)nodes_out, batch);
    gavg_kernel<<<(NGRAPHS * DIM + 255) / 256, 256>>>();
    sgemm_kernel<2><<<dim3(4, NGRAPHS / 128), 256>>>(
        (const float*)pGa, out_w, out, NGRAPHS,
        out_b, nullptr, nullptr, nullptr);

    if (has_batch)
        batch_copy_kernel<<<(NNODES + 255) / 256, 256>>>(batch, out + GSZ + NSZ);
}

// round 17
// speedup vs baseline: 1.3710x; 1.0103x over previous
#include <cuda_runtime.h>
#include <math.h>

// Problem constants (fixed shapes)
#define NNODES  100000
#define NHEDGES 50000
#define NINC    300000
#define NGRAPHS 1024
#define DIN     49
#define DIM     512
#define NLAYERS 3

// ---------------------------------------------------------------------------
// Scratch (static device globals; no runtime allocation allowed)
// ---------------------------------------------------------------------------
__device__ __align__(16) float g_x[(size_t)NNODES * DIM];      // node features
__device__ __align__(16) float g_A[(size_t)NHEDGES * DIM];     // hedge aggregate / B
__device__ __align__(16) float g_msg[(size_t)NHEDGES * DIM];   // hedge_msg
__device__ __align__(16) float g_Wh[(size_t)DIM * DIM];        // weight tf32-hi
__device__ __align__(16) float g_Wl[(size_t)DIM * DIM];        // weight tf32-lo
__device__ int   g_hcnt[NHEDGES];
__device__ int   g_ncnt[NNODES];
__device__ int   g_gcnt[NGRAPHS];
__device__ int   g_hoff[NHEDGES];        // CSR offsets (hedge segments)
__device__ int   g_noff[NNODES];         // CSR offsets (node segments)
__device__ int   g_hcur[NHEDGES];        // scatter cursors
__device__ int   g_ncur[NNODES];
__device__ int   g_hedge_nodes[NINC];    // per-hedge list of node ids
__device__ int   g_node_hedges[NINC];    // per-node list of hedge ids
__device__ __align__(16) float g_gsum[NGRAPHS * DIM];
__device__ __align__(16) float g_gavg[NGRAPHS * DIM];

// ---------------------------------------------------------------------------
// Small PTX helpers (no external headers)
// ---------------------------------------------------------------------------
__device__ __forceinline__ void cp_async16(void* smem_dst, const void* gmem_src)
{
    unsigned s = (unsigned)__cvta_generic_to_shared(smem_dst);
    asm volatile("cp.async.cg.shared.global [%0], [%1], 16;\n" :: "r"(s), "l"(gmem_src));
}
__device__ __forceinline__ void cp_async_commit() { asm volatile("cp.async.commit_group;\n"); }
__device__ __forceinline__ void cp_async_wait_all() { asm volatile("cp.async.wait_all;\n" ::: "memory"); }

__device__ __forceinline__ void red_add_v4(float* p, float4 v)
{
#if defined(__CUDA_ARCH__) && (__CUDA_ARCH__ >= 900)
    asm volatile("red.global.add.v4.f32 [%0], {%1, %2, %3, %4};\n"
                 :: "l"(p), "f"(v.x), "f"(v.y), "f"(v.z), "f"(v.w) : "memory");
#else
    atomicAdd(p + 0, v.x);
    atomicAdd(p + 1, v.y);
    atomicAdd(p + 2, v.z);
    atomicAdd(p + 3, v.w);
#endif
}

__device__ __forceinline__ unsigned tf32_of(float x)
{
    unsigned r;
    asm("cvt.rna.tf32.f32 %0, %1;" : "=r"(r) : "f"(x));
    return r;
}

#define MMA8(d, a0, a1, a2, a3, b0, b1) \
    asm volatile("mma.sync.aligned.m16n8k8.row.col.f32.tf32.tf32.f32 " \
        "{%0,%1,%2,%3},{%4,%5,%6,%7},{%8,%9},{%0,%1,%2,%3};" \
        : "+f"((d)[0]), "+f"((d)[1]), "+f"((d)[2]), "+f"((d)[3]) \
        : "r"(a0), "r"(a1), "r"(a2), "r"(a3), "r"(b0), "r"(b1))

// ---------------------------------------------------------------------------
// Weight split: Wh = tf32(W), Wl = tf32(W - Wh)   (once per GEMM)
// ---------------------------------------------------------------------------
__global__ void w_split_kernel(const float* __restrict__ W)
{
    int i = blockIdx.x * blockDim.x + threadIdx.x;
    if (i < DIM * DIM) {
        float w = W[i];
        unsigned h = tf32_of(w);
        g_Wh[i] = __uint_as_float(h);
        g_Wl[i] = __uint_as_float(tf32_of(w - __uint_as_float(h)));
    }
}

// ---------------------------------------------------------------------------
// Degree / count kernel (fused): incidence degrees + per-graph node counts
// ---------------------------------------------------------------------------
__global__ void count_all_kernel(const int* __restrict__ node_idx,
                                 const int* __restrict__ hedge_idx,
                                 const int* __restrict__ batch)
{
    int e = blockIdx.x * blockDim.x + threadIdx.x;
    if (e < NINC) {
        atomicAdd(&g_ncnt[node_idx[e]], 1);
        atomicAdd(&g_hcnt[hedge_idx[e]], 1);
    }
    if (e < NNODES) {
        atomicAdd(&g_gcnt[batch[e]], 1);
    }
}

// ---------------------------------------------------------------------------
// Exclusive scan (single block, 1024 threads)
// ---------------------------------------------------------------------------
__global__ __launch_bounds__(1024)
void scan_kernel(const int* __restrict__ cnt, int* __restrict__ off, int n)
{
    __shared__ int part[1024];
    const int t = threadIdx.x;
    const int chunk = (n + 1023) / 1024;
    const int lo = t * chunk;
    const int hi = (lo + chunk < n) ? lo + chunk : n;

    int s = 0;
    for (int i = lo; i < hi; i++) s += cnt[i];
    part[t] = s;
    __syncthreads();
    if (t == 0) {
        int run = 0;
        for (int i = 0; i < 1024; i++) { int tmp = part[i]; part[i] = run; run += tmp; }
    }
    __syncthreads();
    int run = part[t];
    for (int i = lo; i < hi; i++) { off[i] = run; run += cnt[i]; }
}

// ---------------------------------------------------------------------------
// CSR scatter: fill adjacency lists (cursor atomics)
// ---------------------------------------------------------------------------
__global__ void csr_fill_kernel(const int* __restrict__ node_idx,
                                const int* __restrict__ hedge_idx)
{
    int e = blockIdx.x * blockDim.x + threadIdx.x;
    if (e >= NINC) return;
    int nid = node_idx[e];
    int hid = hedge_idx[e];
    int ph = atomicAdd(&g_hcur[hid], 1);
    g_hedge_nodes[g_hoff[hid] + ph] = nid;
    int pn = atomicAdd(&g_ncur[nid], 1);
    g_node_hedges[g_noff[nid] + pn] = hid;
}

// ---------------------------------------------------------------------------
// Input GEMM: x = node_features[100000,49] @ in_w[49,512] + in_b
// ---------------------------------------------------------------------------
__global__ __launch_bounds__(128)
void input_gemm_kernel(const float* __restrict__ nf,
                       const float* __restrict__ w,
                       const float* __restrict__ b)
{
    __shared__ float snf[16 * DIN];
    const int r0 = blockIdx.x * 16;
    const int tid = threadIdx.x;
    for (int i = tid; i < 16 * DIN; i += 128)
        snf[i] = nf[(size_t)r0 * DIN + i];   // rows contiguous
    __syncthreads();

    const int c0 = tid * 4;
    float4 acc[16];
#pragma unroll
    for (int r = 0; r < 16; r++) acc[r] = make_float4(0.f, 0.f, 0.f, 0.f);

    for (int k = 0; k < DIN; k++) {
        float4 w4 = *(const float4*)&w[(size_t)k * DIM + c0];
#pragma unroll
        for (int r = 0; r < 16; r++) {
            float a = snf[r * DIN + k];
            acc[r].x = fmaf(a, w4.x, acc[r].x);
            acc[r].y = fmaf(a, w4.y, acc[r].y);
            acc[r].z = fmaf(a, w4.z, acc[r].z);
            acc[r].w = fmaf(a, w4.w, acc[r].w);
        }
    }
    float4 bb = *(const float4*)&b[c0];
#pragma unroll
    for (int r = 0; r < 16; r++) {
        float4 v = acc[r];
        v.x += bb.x; v.y += bb.y; v.z += bb.z; v.w += bb.w;
        *(float4*)&g_x[(size_t)(r0 + r) * DIM + c0] = v;
    }
}

// ---------------------------------------------------------------------------
// Hedge gather: A[h] = sum over nodes in hedge h of x[node]  (CSR, no atomics)
// ---------------------------------------------------------------------------
__global__ __launch_bounds__(128)
void hedge_gather_kernel(const float* __restrict__ x, float* __restrict__ A)
{
    const int h = blockIdx.x;
    const int c = threadIdx.x * 4;
    const int start = g_hoff[h];
    const int deg = g_hcnt[h];
    float4 acc = make_float4(0.f, 0.f, 0.f, 0.f);
    for (int j = 0; j < deg; j++) {
        int nid = g_hedge_nodes[start + j];   // broadcast load
        float4 v = *(const float4*)&x[(size_t)nid * DIM + c];
        acc.x += v.x; acc.y += v.y; acc.z += v.z; acc.w += v.w;
    }
    *(float4*)&A[(size_t)h * DIM + c] = acc;
}

// ---------------------------------------------------------------------------
// SGEMM via split-TF32 tensor cores, W pre-split in global memory.
// C[M,512] = A[M,512] @ W[512,512]
// MODE 0: plain   MODE 1: hedge_msg epilogue   MODE 2: + column bias
// 128x128 tile, KT=8, 256 threads = 8 warps (4Mx2N), warp tile 32x64.
// A: register-staged, split to tf32 hi/lo, stored PRE-PERMUTED into fragment
//    layout. B: cp.async of Wh and Wl tiles -> inner loop is cvt-free.
// D = Ah*Bh + Ah*Bl + Al*Bh.
// ---------------------------------------------------------------------------
template<int MODE>
__global__ __launch_bounds__(256, 2)
void sgemm_kernel(const float* __restrict__ A,
                  const float* __restrict__ Wh, const float* __restrict__ Wl,
                  float* __restrict__ C, int M,
                  const float* __restrict__ colbias,
                  const int* __restrict__ cnt,
                  const int* __restrict__ types,
                  const float* __restrict__ type_emb)
{
    __shared__ __align__(16) float sAh[2][8][32][4];
    __shared__ __align__(16) float sAl[2][8][32][4];
    __shared__ __align__(16) float sBh[2][8][136];
    __shared__ __align__(16) float sBl[2][8][136];

    const int tid  = threadIdx.x;
    const int lane = tid & 31;
    const int wid  = tid >> 5;           // 0..7
    const int wm   = wid & 3;            // warp row group
    const int wn0  = (wid >> 2) * 64;    // warp col base
    const int g    = lane >> 2;
    const int t4   = lane & 3;
    const int row0 = blockIdx.y * 128;
    const int col0 = blockIdx.x * 128;

    // A staging: thread owns row am, k-half ak4
    const int am   = tid >> 1;            // 0..127
    const int ak4  = (tid & 1) * 4;       // 0 or 4
    const int asub = am >> 4;             // subtile 0..7
    const int alan = (am & 7) * 4;        // lane base (j added)
    const int aidx = (tid & 1) * 2 + ((am >> 3) & 1);  // fragment reg index
    // B staging
    const int bk  = tid >> 5;             // 0..7
    const int bn4 = (tid & 31) * 4;       // 0..124

    float acc[2][8][4];
#pragma unroll
    for (int s = 0; s < 2; s++)
#pragma unroll
        for (int nt = 0; nt < 8; nt++)
#pragma unroll
            for (int r = 0; r < 4; r++) acc[s][nt][r] = 0.f;

    float4 va;

    // ---- prologue: stage K-tile 0
    {
        int gr = row0 + am;
        va = (gr < M) ? *(const float4*)&A[(size_t)gr * DIM + ak4]
                      : make_float4(0.f, 0.f, 0.f, 0.f);
        cp_async16(&sBh[0][bk][bn4], &Wh[(size_t)bk * DIM + col0 + bn4]);
        cp_async16(&sBl[0][bk][bn4], &Wl[(size_t)bk * DIM + col0 + bn4]);
        cp_async_commit();
        float xs[4] = {va.x, va.y, va.z, va.w};
#pragma unroll
        for (int j = 0; j < 4; j++) {
            unsigned h = tf32_of(xs[j]);
            unsigned l = tf32_of(xs[j] - __uint_as_float(h));
            sAh[0][asub][alan + j][aidx] = __uint_as_float(h);
            sAl[0][asub][alan + j][aidx] = __uint_as_float(l);
        }
        cp_async_wait_all();
        __syncthreads();
    }

    const int NT = DIM / 8;   // 64 K-tiles
    for (int tt = 0; tt < NT; tt++) {
        const int cur = tt & 1;
        const int nxt = cur ^ 1;
        // ---- prefetch tile tt+1
        if (tt + 1 < NT) {
            const int k0 = (tt + 1) * 8;
            int gr = row0 + am;
            va = (gr < M) ? *(const float4*)&A[(size_t)gr * DIM + k0 + ak4]
                          : make_float4(0.f, 0.f, 0.f, 0.f);
            cp_async16(&sBh[nxt][bk][bn4], &Wh[(size_t)(k0 + bk) * DIM + col0 + bn4]);
            cp_async16(&sBl[nxt][bk][bn4], &Wl[(size_t)(k0 + bk) * DIM + col0 + bn4]);
            cp_async_commit();
        }
        // ---- A fragments: one LDS.128 each (pre-permuted layout)
        float4 fh0 = *(const float4*)&sAh[cur][wm * 2 + 0][lane][0];
        float4 fh1 = *(const float4*)&sAh[cur][wm * 2 + 1][lane][0];
        float4 fl0 = *(const float4*)&sAl[cur][wm * 2 + 0][lane][0];
        float4 fl1 = *(const float4*)&sAl[cur][wm * 2 + 1][lane][0];
        unsigned ah0[4] = {__float_as_uint(fh0.x), __float_as_uint(fh0.y),
                           __float_as_uint(fh0.z), __float_as_uint(fh0.w)};
        unsigned ah1[4] = {__float_as_uint(fh1.x), __float_as_uint(fh1.y),
                           __float_as_uint(fh1.z), __float_as_uint(fh1.w)};
        unsigned al0[4] = {__float_as_uint(fl0.x), __float_as_uint(fl0.y),
                           __float_as_uint(fl0.z), __float_as_uint(fl0.w)};
        unsigned al1[4] = {__float_as_uint(fl1.x), __float_as_uint(fl1.y),
                           __float_as_uint(fl1.z), __float_as_uint(fl1.w)};
#pragma unroll
        for (int nt = 0; nt < 8; nt++) {
            unsigned bh0 = __float_as_uint(sBh[cur][t4][wn0 + nt * 8 + g]);
            unsigned bh1 = __float_as_uint(sBh[cur][t4 + 4][wn0 + nt * 8 + g]);
            unsigned bl0 = __float_as_uint(sBl[cur][t4][wn0 + nt * 8 + g]);
            unsigned bl1 = __float_as_uint(sBl[cur][t4 + 4][wn0 + nt * 8 + g]);
            MMA8(acc[0][nt], ah0[0], ah0[1], ah0[2], ah0[3], bh0, bh1);
            MMA8(acc[0][nt], ah0[0], ah0[1], ah0[2], ah0[3], bl0, bl1);
            MMA8(acc[0][nt], al0[0], al0[1], al0[2], al0[3], bh0, bh1);
            MMA8(acc[1][nt], ah1[0], ah1[1], ah1[2], ah1[3], bh0, bh1);
            MMA8(acc[1][nt], ah1[0], ah1[1], ah1[2], ah1[3], bl0, bl1);
            MMA8(acc[1][nt], al1[0], al1[1], al1[2], al1[3], bh0, bh1);
        }
        // ---- store staged tile tt+1, sync
        if (tt + 1 < NT) {
            float xs[4] = {va.x, va.y, va.z, va.w};
#pragma unroll
            for (int j = 0; j < 4; j++) {
                unsigned h = tf32_of(xs[j]);
                unsigned l = tf32_of(xs[j] - __uint_as_float(h));
                sAh[nxt][asub][alan + j][aidx] = __uint_as_float(h);
                sAl[nxt][asub][alan + j][aidx] = __uint_as_float(l);
            }
            cp_async_wait_all();
            __syncthreads();
        }
    }

    // ---- epilogue: lane (g,t4) owns rows {wm*32+s*16+g+r8*8}, cols {nt*8+t4*2,+1}
#pragma unroll
    for (int s = 0; s < 2; s++) {
#pragma unroll
        for (int r8 = 0; r8 < 2; r8++) {
            int r = row0 + wm * 32 + s * 16 + g + r8 * 8;
            if (r >= M) continue;
            float invd = 1.f, hb = 0.f;
            const float* te = nullptr;
            if (MODE == 1) {
                int cn = cnt[r];
                invd = 1.f / (float)(cn > 0 ? cn : 1);
                hb   = (cn > 0) ? 1.f : 0.f;
                te   = type_emb + (size_t)types[r] * DIM;
            }
#pragma unroll
            for (int nt = 0; nt < 8; nt++) {
                int c = col0 + wn0 + nt * 8 + t4 * 2;
                float v0 = acc[s][nt][r8 * 2 + 0];
                float v1 = acc[s][nt][r8 * 2 + 1];
                if (MODE == 1) {
                    v0 = v0 * invd + hb * colbias[c + 0] + te[c + 0];
                    v1 = v1 * invd + hb * colbias[c + 1] + te[c + 1];
                } else if (MODE == 2) {
                    v0 += colbias[c + 0];
                    v1 += colbias[c + 1];
                }
                *(float2*)&C[(size_t)r * DIM + c] = make_float2(v0, v1);
            }
        }
    }
}

// ---------------------------------------------------------------------------
// Fused node gather + epilogue: out = gelu(LN(x + (sum_h B[h])/deg + b2))
// ---------------------------------------------------------------------------
__device__ __forceinline__ float gelu_exact(float y)
{
    return 0.5f * y * (1.f + erff(y * 0.70710678118654752440f));
}

__global__ __launch_bounds__(128)
void node_epilogue_kernel(const float* __restrict__ xin,
                          const float* __restrict__ B,
                          float* __restrict__ xout,
                          const float* __restrict__ b2,
                          const float* __restrict__ lng,
                          const float* __restrict__ lnb)
{
    const int n = blockIdx.x;
    const int t = threadIdx.x;
    const size_t base = (size_t)n * DIM + t * 4;
    const int cn = g_ncnt[n];
    const float invd = 1.f / (float)(cn > 0 ? cn : 1);
    const int start = g_noff[n];

    float4 a = make_float4(0.f, 0.f, 0.f, 0.f);
    for (int j = 0; j < cn; j++) {
        int hid = g_node_hedges[start + j];
        float4 v = *(const float4*)&B[(size_t)hid * DIM + t * 4];
        a.x += v.x; a.y += v.y; a.z += v.z; a.w += v.w;
    }

    float4 xi = *(const float4*)&xin[base];
    float4 bb = *(const float4*)&b2[t * 4];
    float4 v;
    v.x = fmaf(a.x, invd, bb.x) + xi.x;
    v.y = fmaf(a.y, invd, bb.y) + xi.y;
    v.z = fmaf(a.z, invd, bb.z) + xi.z;
    v.w = fmaf(a.w, invd, bb.w) + xi.w;

    float s = v.x + v.y + v.z + v.w;
    float q = v.x * v.x + v.y * v.y + v.z * v.z + v.w * v.w;
#pragma unroll
    for (int o = 16; o; o >>= 1) {
        s += __shfl_xor_sync(0xffffffffu, s, o);
        q += __shfl_xor_sync(0xffffffffu, q, o);
    }
    __shared__ float ss[4], sq[4];
    if ((t & 31) == 0) { ss[t >> 5] = s; sq[t >> 5] = q; }
    __syncthreads();
    s = ss[0] + ss[1] + ss[2] + ss[3];
    q = sq[0] + sq[1] + sq[2] + sq[3];

    const float mean = s * (1.f / 512.f);
    const float var  = q * (1.f / 512.f) - mean * mean;
    const float rstd = rsqrtf(var + 1e-5f);

    float4 gg = *(const float4*)&lng[t * 4];
    float4 lb = *(const float4*)&lnb[t * 4];
    float4 o;
    o.x = gelu_exact(fmaf((v.x - mean) * rstd, gg.x, lb.x));
    o.y = gelu_exact(fmaf((v.y - mean) * rstd, gg.y, lb.y));
    o.z = gelu_exact(fmaf((v.z - mean) * rstd, gg.z, lb.z));
    o.w = gelu_exact(fmaf((v.w - mean) * rstd, gg.w, lb.w));
    *(float4*)&xout[base] = o;
}

// ---------------------------------------------------------------------------
// Graph pooling
// ---------------------------------------------------------------------------
__global__ __launch_bounds__(128)
void pool_kernel(const float* __restrict__ xsrc, const int* __restrict__ batch)
{
    const int n = blockIdx.x;
    const int t = threadIdx.x;
    const int b = batch[n];
    float4 v = *(const float4*)&xsrc[(size_t)n * DIM + t * 4];
    red_add_v4(&g_gsum[(size_t)b * DIM + t * 4], v);
}

__global__ void gavg_kernel()
{
    int i = blockIdx.x * blockDim.x + threadIdx.x;
    if (i < NGRAPHS * DIM) {
        int g = i >> 9;
        int cn = g_gcnt[g];
        g_gavg[i] = g_gsum[i] / (float)(cn > 0 ? cn : 1);
    }
}

__global__ void batch_copy_kernel(const int* __restrict__ batch, float* __restrict__ out)
{
    int n = blockIdx.x * blockDim.x + threadIdx.x;
    if (n < NNODES) out[n] = (float)batch[n];
}

// ---------------------------------------------------------------------------
// Launch
// ---------------------------------------------------------------------------
extern "C" void kernel_launch(void* const* d_in, const int* in_sizes, int n_in,
                              void* d_out, int out_size)
{
    const float* nf        = (const float*)d_in[0];
    const int*   node_idx  = (const int*)d_in[1];
    const int*   hedge_idx = (const int*)d_in[2];
    const int*   htypes    = (const int*)d_in[3];
    const int*   batch     = (const int*)d_in[4];

    // Locate weight block robustly (optional scalar num_graphs input may be at index 5)
    int w = 5;
    for (int i = 5; i < n_in; i++) {
        if (in_sizes[i] == DIN * DIM) { w = i; break; }
    }
    const float* in_w     = (const float*)d_in[w + 0];
    const float* in_b     = (const float*)d_in[w + 1];
    const float* type_emb = (const float*)d_in[w + 2];
    const float* l1_w     = (const float*)d_in[w + 3];
    const float* l1_b     = (const float*)d_in[w + 4];
    const float* l2_w     = (const float*)d_in[w + 5];
    const float* l2_b     = (const float*)d_in[w + 6];
    const float* ln_g     = (const float*)d_in[w + 7];
    const float* ln_b     = (const float*)d_in[w + 8];
    const float* out_w    = (const float*)d_in[w + 9];
    const float* out_b    = (const float*)d_in[w + 10];

    float* out = (float*)d_out;

    // Symbol addresses (lookup only; capture-safe)
    void *pX, *pA, *pMsg, *pHc, *pNc, *pGc, *pGs, *pGa, *pWh, *pWl;
    void *pHoff, *pNoff, *pHcur, *pNcur;
    cudaGetSymbolAddress(&pX, g_x);
    cudaGetSymbolAddress(&pA, g_A);
    cudaGetSymbolAddress(&pMsg, g_msg);
    cudaGetSymbolAddress(&pHc, g_hcnt);
    cudaGetSymbolAddress(&pNc, g_ncnt);
    cudaGetSymbolAddress(&pGc, g_gcnt);
    cudaGetSymbolAddress(&pGs, g_gsum);
    cudaGetSymbolAddress(&pGa, g_gavg);
    cudaGetSymbolAddress(&pWh, g_Wh);
    cudaGetSymbolAddress(&pWl, g_Wl);
    cudaGetSymbolAddress(&pHoff, g_hoff);
    cudaGetSymbolAddress(&pNoff, g_noff);
    cudaGetSymbolAddress(&pHcur, g_hcur);
    cudaGetSymbolAddress(&pNcur, g_ncur);

    const size_t GSZ = (size_t)NGRAPHS * DIM;           // 524288
    const size_t NSZ = (size_t)NNODES * DIM;            // 51200000
    const bool has_nodes = (size_t)out_size >= GSZ + NSZ;
    const bool has_batch = (size_t)out_size >= GSZ + NSZ + NNODES;
    float* nodes_out = has_nodes ? out + GSZ : (float*)pX;

    // Degrees + CSR build
    cudaMemsetAsync(pHc, 0, sizeof(int) * NHEDGES, 0);
    cudaMemsetAsync(pNc, 0, sizeof(int) * NNODES, 0);
    cudaMemsetAsync(pGc, 0, sizeof(int) * NGRAPHS, 0);
    count_all_kernel<<<(NINC + 255) / 256, 256>>>(node_idx, hedge_idx, batch);
    scan_kernel<<<1, 1024>>>((const int*)pHc, (int*)pHoff, NHEDGES);
    scan_kernel<<<1, 1024>>>((const int*)pNc, (int*)pNoff, NNODES);
    cudaMemsetAsync(pHcur, 0, sizeof(int) * NHEDGES, 0);
    cudaMemsetAsync(pNcur, 0, sizeof(int) * NNODES, 0);
    csr_fill_kernel<<<(NINC + 255) / 256, 256>>>(node_idx, hedge_idx);

    // Input projection
    input_gemm_kernel<<<NNODES / 16, 128>>>(nf, in_w, in_b);

    const dim3 gemm_grid_h(4, (NHEDGES + 127) / 128);
    const int WSPLIT_G = (DIM * DIM + 255) / 256;
    const float* Wh = (const float*)pWh;
    const float* Wl = (const float*)pWl;

    for (int i = 0; i < NLAYERS; i++) {
        // A[h] = sum of x rows in hedge h (CSR gather, no atomics/memset)
        hedge_gather_kernel<<<NHEDGES, 128>>>((const float*)pX, (float*)pA);
        // msg = (A@W1 + cnt*b1)/clip(cnt,1) + type_emb[type]
        w_split_kernel<<<WSPLIT_G, 256>>>(l1_w + (size_t)i * DIM * DIM);
        sgemm_kernel<1><<<gemm_grid_h, 256>>>(
            (const float*)pA, Wh, Wl, (float*)pMsg, NHEDGES,
            l1_b + (size_t)i * DIM, (const int*)pHc, htypes, type_emb);
        // B = msg @ W2   (reuse g_A)
        w_split_kernel<<<WSPLIT_G, 256>>>(l2_w + (size_t)i * DIM * DIM);
        sgemm_kernel<0><<<gemm_grid_h, 256>>>(
            (const float*)pMsg, Wh, Wl, (float*)pA, NHEDGES,
            nullptr, nullptr, nullptr, nullptr);
        // x = gelu(LN(x + csr_gather(B)/deg + b2))   (fused gather+epilogue)
        float* xo = (i == NLAYERS - 1) ? nodes_out : (float*)pX;
        node_epilogue_kernel<<<NNODES, 128>>>(
            (const float*)pX, (const float*)pA, xo,
            l2_b + (size_t)i * DIM, ln_g + (size_t)i * DIM, ln_b + (size_t)i * DIM);
    }

    // Graph pooling + output projection
    cudaMemsetAsync(pGs, 0, sizeof(float) * GSZ, 0);
    pool_kernel<<<NNODES, 128>>>((const float*)nodes_out, batch);
    gavg_kernel<<<(NGRAPHS * DIM + 255) / 256, 256>>>();
    w_split_kernel<<<WSPLIT_G, 256>>>(out_w);
    sgemm_kernel<2><<<dim3(4, NGRAPHS / 128), 256>>>(
        (const float*)pGa, Wh, Wl, out, NGRAPHS,
        out_b, nullptr, nullptr, nullptr);

    if (has_batch)
        batch_copy_kernel<<<(NNODES + 255) / 256, 256>>>(batch, out + GSZ + NSZ);
}